// round 6
// baseline (speedup 1.0000x reference)
#include <cuda_runtime.h>
#include <cuda_fp16.h>
#include <cstdint>

#define N_NODES 100000
#define N_EDGES 1600000
#define HID 64
#define NG 512
#define NCLS 10
#define SCAN_BS 512
#define SCAN_NB ((N_NODES + SCAN_BS - 1) / SCAN_BS)   // 196
#define AGG_STRIDE 72   // padded smem stride (halves) -> conflict-free LDS

// ---------------- device scratch (no allocations allowed) -------------------
__device__ __half g_h0[N_NODES * HID];
__device__ __half g_h1[N_NODES * HID];
__device__ __half g_wT[4 * 4096];   // wT[m][n*64+k] = w[k][n], fp16
__device__ int   g_cnt[N_NODES];
__device__ int   g_rowptr[N_NODES + 1];
__device__ int   g_cursor[N_NODES];
__device__ int   g_eord[N_EDGES];
__device__ int   g_part[SCAN_NB];
__device__ float g_pool[NG * HID];
__device__ int   g_pcnt[NG];

// ---------------------------------------------------------------------------
__global__ void k_zero() {
    int i = blockIdx.x * blockDim.x + threadIdx.x;
    if (i < N_NODES) g_cnt[i] = 0;
    if (i < NG * HID) g_pool[i] = 0.f;
    if (i < NG) g_pcnt[i] = 0;
}

// Embedding: h0 = concat(semb[x0], cemb[x1]) in fp16. 8 threads/node.
__global__ void k_embed(const int* __restrict__ x,
                        const int* __restrict__ batch,
                        const float* __restrict__ semb,
                        const float* __restrict__ cemb) {
    int t = blockIdx.x * blockDim.x + threadIdx.x;   // N_NODES*8
    int node = t >> 3, j = t & 7;
    const float4* src;
    if (j < 4) {
        int s = x[node * 2 + 0];
        src = (const float4*)&semb[s * 32 + j * 8];
    } else {
        int c = x[node * 2 + 1];
        src = (const float4*)&cemb[c * 32 + (j - 4) * 8];
    }
    float4 a = src[0], b = src[1];
    __half2 p0 = __floats2half2_rn(a.x, a.y);
    __half2 p1 = __floats2half2_rn(a.z, a.w);
    __half2 p2 = __floats2half2_rn(b.x, b.y);
    __half2 p3 = __floats2half2_rn(b.z, b.w);
    uint4 o = make_uint4(*(uint32_t*)&p0, *(uint32_t*)&p1,
                         *(uint32_t*)&p2, *(uint32_t*)&p3);
    *(uint4*)&g_h0[node * 64 + j * 8] = o;
    if (j == 0) atomicAdd(&g_pcnt[batch[node]], 1);
}

// Transpose weights to k-major fp16: wT[n][k] = w[k][n]
__global__ void k_prepw(const float* __restrict__ w0,
                        const float* __restrict__ w1,
                        const float* __restrict__ w2,
                        const float* __restrict__ w3) {
    int id = blockIdx.x * blockDim.x + threadIdx.x;   // 16384
    int m = id >> 12, r = id & 4095;
    int n = r >> 6, k = r & 63;
    const float* w = (m == 0) ? w0 : (m == 1) ? w1 : (m == 2) ? w2 : w3;
    g_wT[m * 4096 + n * 64 + k] = __float2half_rn(w[k * 64 + n]);
}

// In-degree histogram, 4 edges/thread via int4
__global__ void k_count(const int* __restrict__ ei) {
    int e = blockIdx.x * blockDim.x + threadIdx.x;
    if (e >= N_EDGES / 4) return;
    int4 t4 = ((const int4*)(ei + N_EDGES))[e];
    atomicAdd(&g_cnt[t4.x], 1);
    atomicAdd(&g_cnt[t4.y], 1);
    atomicAdd(&g_cnt[t4.z], 1);
    atomicAdd(&g_cnt[t4.w], 1);
}

__global__ void k_scan1() {
    __shared__ int s[SCAN_BS];
    int tid = threadIdx.x;
    int i = blockIdx.x * SCAN_BS + tid;
    int v = (i < N_NODES) ? g_cnt[i] : 0;
    s[tid] = v;
    __syncthreads();
    for (int off = 1; off < SCAN_BS; off <<= 1) {
        int t = (tid >= off) ? s[tid - off] : 0;
        __syncthreads();
        s[tid] += t;
        __syncthreads();
    }
    if (i < N_NODES) g_rowptr[i] = s[tid] - v;
    if (tid == SCAN_BS - 1) g_part[blockIdx.x] = s[tid];
}

__global__ void k_scan2() {
    int lane = threadIdx.x;
    int carry = 0;
    for (int base = 0; base < SCAN_NB; base += 32) {
        int idx = base + lane;
        int orig = (idx < SCAN_NB) ? g_part[idx] : 0;
        int v = orig;
        #pragma unroll
        for (int off = 1; off < 32; off <<= 1) {
            int t = __shfl_up_sync(0xffffffffu, v, off);
            if (lane >= off) v += t;
        }
        if (idx < SCAN_NB) g_part[idx] = carry + v - orig;
        carry += __shfl_sync(0xffffffffu, v, 31);
    }
}

__global__ void k_scan3() {
    int i = blockIdx.x * blockDim.x + threadIdx.x;
    if (i < N_NODES) {
        int r = g_rowptr[i] + g_part[i / SCAN_BS];
        g_rowptr[i] = r;
        g_cursor[i] = r;
    }
    if (i == 0) g_rowptr[N_NODES] = N_EDGES;
}

// Bucket edges by target, 4 edges/thread via int4
__global__ void k_bucket(const int* __restrict__ ei) {
    int e = blockIdx.x * blockDim.x + threadIdx.x;
    if (e >= N_EDGES / 4) return;
    int4 s4 = ((const int4*)ei)[e];
    int4 t4 = ((const int4*)(ei + N_EDGES))[e];
    int p0 = atomicAdd(&g_cursor[t4.x], 1);
    int p1 = atomicAdd(&g_cursor[t4.y], 1);
    int p2 = atomicAdd(&g_cursor[t4.z], 1);
    int p3 = atomicAdd(&g_cursor[t4.w], 1);
    g_eord[p0] = s4.x;
    g_eord[p1] = s4.y;
    g_eord[p2] = s4.z;
    g_eord[p3] = s4.w;
}

// ---------------------------------------------------------------------------
// Fused gather + HMMA update: one block = 128 nodes.
// Phase 1: each warp mean-gathers 16 nodes into padded smem (fp16).
// Phase 2: out = relu(agg @ wl + h @ wr + b) via mma.sync.m16n8k16,
//          kc=0 A-operand from smem, kc=1 from gmem.
__global__ void __launch_bounds__(256) k_gupd(const float* __restrict__ bias,
                                              const int* __restrict__ batch,
                                              int layer) {
    __shared__ __half sAgg[128 * AGG_STRIDE];   // 18 KB, padded rows
    __shared__ float sbias[64];
    int tid = threadIdx.x;
    int wid = tid >> 5, lane = tid & 31;
    if (tid < 64) sbias[tid] = bias[tid];

    const __half* __restrict__ hin = layer ? g_h1 : g_h0;
    int nb = blockIdx.x * 128;

    // ---- Phase 1: gather 16 nodes per warp ----
    for (int i = 0; i < 16; i++) {
        int node = nb + wid * 16 + i;
        float2 acc = make_float2(0.f, 0.f);
        if (node < N_NODES) {
            int start = g_rowptr[node], end = g_rowptr[node + 1];
            for (int base = start; base < end; base += 32) {
                int p = base + lane;
                int idx = (p < end) ? g_eord[p] : 0;
                int m = min(32, end - base);
                int j = 0;
                for (; j + 4 <= m; j += 4) {
                    int s0 = __shfl_sync(0xffffffffu, idx, j);
                    int s1 = __shfl_sync(0xffffffffu, idx, j + 1);
                    int s2 = __shfl_sync(0xffffffffu, idx, j + 2);
                    int s3 = __shfl_sync(0xffffffffu, idx, j + 3);
                    __half2 v0 = *(const __half2*)&hin[(size_t)s0 * 64 + lane * 2];
                    __half2 v1 = *(const __half2*)&hin[(size_t)s1 * 64 + lane * 2];
                    __half2 v2 = *(const __half2*)&hin[(size_t)s2 * 64 + lane * 2];
                    __half2 v3 = *(const __half2*)&hin[(size_t)s3 * 64 + lane * 2];
                    float2 f0 = __half22float2(v0);
                    float2 f1 = __half22float2(v1);
                    float2 f2 = __half22float2(v2);
                    float2 f3 = __half22float2(v3);
                    acc.x += (f0.x + f1.x) + (f2.x + f3.x);
                    acc.y += (f0.y + f1.y) + (f2.y + f3.y);
                }
                for (; j < m; j++) {
                    int s = __shfl_sync(0xffffffffu, idx, j);
                    float2 f = __half22float2(
                        *(const __half2*)&hin[(size_t)s * 64 + lane * 2]);
                    acc.x += f.x;
                    acc.y += f.y;
                }
            }
            float inv = 1.f / (float)max(end - start, 1);
            acc.x *= inv; acc.y *= inv;
        }
        __half2 o = __floats2half2_rn(acc.x, acc.y);
        *(__half2*)&sAgg[(wid * 16 + i) * AGG_STRIDE + lane * 2] = o;
    }
    __syncthreads();

    // ---- Phase 2: HMMA ----
    int m0 = wid * 16;             // local row base within block tile
    int qp = (lane & 3) * 2;       // k-pair offset within 16
    int gi = lane >> 2;            // group index 0..7
    int r0l = m0 + gi;             // local rows
    int r1l = r0l + 8;
    int r0 = nb + r0l, r1 = nb + r1l;
    bool v0 = r0 < N_NODES, v1 = r1 < N_NODES;

    float acc[8][4];
    #pragma unroll
    for (int t = 0; t < 8; t++)
        #pragma unroll
        for (int i = 0; i < 4; i++) acc[t][i] = 0.f;

    #pragma unroll
    for (int kc = 0; kc < 2; kc++) {
        const __half* __restrict__ W = &g_wT[(layer * 2 + kc) * 4096];
        #pragma unroll
        for (int ks = 0; ks < 4; ks++) {
            int kb = ks * 16;
            uint32_t a0, a1, a2, a3;
            if (kc == 0) {
                a0 = *(const uint32_t*)&sAgg[r0l * AGG_STRIDE + kb + qp];
                a1 = *(const uint32_t*)&sAgg[r1l * AGG_STRIDE + kb + qp];
                a2 = *(const uint32_t*)&sAgg[r0l * AGG_STRIDE + kb + qp + 8];
                a3 = *(const uint32_t*)&sAgg[r1l * AGG_STRIDE + kb + qp + 8];
            } else {
                a0 = a1 = a2 = a3 = 0;
                if (v0) {
                    a0 = *(const uint32_t*)&hin[(size_t)r0 * 64 + kb + qp];
                    a2 = *(const uint32_t*)&hin[(size_t)r0 * 64 + kb + qp + 8];
                }
                if (v1) {
                    a1 = *(const uint32_t*)&hin[(size_t)r1 * 64 + kb + qp];
                    a3 = *(const uint32_t*)&hin[(size_t)r1 * 64 + kb + qp + 8];
                }
            }
            #pragma unroll
            for (int t = 0; t < 8; t++) {
                int n = t * 8 + gi;
                uint32_t b0 = *(const uint32_t*)&W[n * 64 + kb + qp];
                uint32_t b1 = *(const uint32_t*)&W[n * 64 + kb + qp + 8];
                asm volatile(
                    "mma.sync.aligned.m16n8k16.row.col.f32.f16.f16.f32 "
                    "{%0,%1,%2,%3}, {%4,%5,%6,%7}, {%8,%9}, {%0,%1,%2,%3};"
                    : "+f"(acc[t][0]), "+f"(acc[t][1]),
                      "+f"(acc[t][2]), "+f"(acc[t][3])
                    : "r"(a0), "r"(a1), "r"(a2), "r"(a3), "r"(b0), "r"(b1));
            }
        }
    }

    // epilogue: bias + relu, then store (layer 0) or pool (layer 1)
    int b0g = v0 ? batch[r0] : 0;
    int b1g = v1 ? batch[r1] : 0;
    #pragma unroll
    for (int t = 0; t < 8; t++) {
        int ct = t * 8 + qp;
        float bx = sbias[ct], by = sbias[ct + 1];
        float o0 = fmaxf(acc[t][0] + bx, 0.f);
        float o1 = fmaxf(acc[t][1] + by, 0.f);
        float o2 = fmaxf(acc[t][2] + bx, 0.f);
        float o3 = fmaxf(acc[t][3] + by, 0.f);
        if (layer == 0) {
            if (v0) {
                __half2 p = __floats2half2_rn(o0, o1);
                *(__half2*)&g_h1[(size_t)r0 * 64 + ct] = p;
            }
            if (v1) {
                __half2 p = __floats2half2_rn(o2, o3);
                *(__half2*)&g_h1[(size_t)r1 * 64 + ct] = p;
            }
        } else {
            if (v0) atomicAdd((float2*)&g_pool[b0g * 64 + ct],
                              make_float2(o0, o1));
            if (v1) atomicAdd((float2*)&g_pool[b1g * 64 + ct],
                              make_float2(o2, o3));
        }
    }
}

// ---------------------------------------------------------------------------
__global__ void k_final(const float* __restrict__ wc,
                        const float* __restrict__ bc,
                        float* __restrict__ out) {
    int g = blockIdx.x * blockDim.x + threadIdx.x;
    if (g >= NG) return;
    float inv = 1.f / fmaxf((float)g_pcnt[g], 1.f);
    float acc[NCLS];
    #pragma unroll
    for (int c = 0; c < NCLS; c++) acc[c] = bc[c];
    for (int k = 0; k < 64; k++) {
        float p = g_pool[g * 64 + k] * inv;
        #pragma unroll
        for (int c = 0; c < NCLS; c++)
            acc[c] += p * wc[k * NCLS + c];
    }
    #pragma unroll
    for (int c = 0; c < NCLS; c++) out[g * NCLS + c] = acc[c];
}

// ---------------------------------------------------------------------------
extern "C" void kernel_launch(void* const* d_in, const int* in_sizes, int n_in,
                              void* d_out, int out_size) {
    int o = (n_in >= 14) ? 1 : 0;
    const int*   x     = (const int*)d_in[0];
    const int*   ei    = (const int*)d_in[1];
    const int*   batch = (const int*)d_in[2];
    const float* semb  = (const float*)d_in[3 + o];
    const float* cemb  = (const float*)d_in[4 + o];
    const float* w1l   = (const float*)d_in[5 + o];
    const float* w1r   = (const float*)d_in[6 + o];
    const float* b1    = (const float*)d_in[7 + o];
    const float* w2l   = (const float*)d_in[8 + o];
    const float* w2r   = (const float*)d_in[9 + o];
    const float* b2    = (const float*)d_in[10 + o];
    const float* wc    = (const float*)d_in[11 + o];
    const float* bc    = (const float*)d_in[12 + o];
    float* out = (float*)d_out;

    k_zero<<<(N_NODES + 255) / 256, 256>>>();
    k_embed<<<(N_NODES * 8) / 256, 256>>>(x, batch, semb, cemb);
    k_prepw<<<64, 256>>>(w1l, w1r, w2l, w2r);
    // CSR build (shared by both layers)
    k_count<<<(N_EDGES / 4 + 255) / 256, 256>>>(ei);
    k_scan1<<<SCAN_NB, SCAN_BS>>>();
    k_scan2<<<1, 32>>>();
    k_scan3<<<(N_NODES + 255) / 256, 256>>>();
    k_bucket<<<(N_EDGES / 4 + 255) / 256, 256>>>(ei);
    // layer 1 (fused gather + update)
    k_gupd<<<(N_NODES + 127) / 128, 256>>>(b1, batch, 0);
    // layer 2
    k_gupd<<<(N_NODES + 127) / 128, 256>>>(b2, batch, 1);
    // pool -> classifier
    k_final<<<(NG + 255) / 256, 256>>>(wc, bc, out);
}

// round 8
// speedup vs baseline: 1.0829x; 1.0829x over previous
#include <cuda_runtime.h>
#include <cuda_fp16.h>
#include <cstdint>

#define N_NODES 100000
#define N_EDGES 1600000
#define HID 64
#define NG 512
#define NCLS 10
#define SCAN_BS 512
#define SCAN_NB ((N_NODES + SCAN_BS - 1) / SCAN_BS)   // 196

// ---------------- device scratch (no allocations allowed) -------------------
__device__ __half g_h0[N_NODES * HID];
__device__ __half g_h1[N_NODES * HID];
__device__ __half g_agg[N_NODES * HID];
__device__ __half g_wT[4 * 4096];   // wT[m][n*64+k] = w[k][n], fp16
__device__ int   g_cnt[N_NODES];
__device__ int   g_rowptr[N_NODES + 1];
__device__ int   g_cursor[N_NODES];
__device__ int   g_eord[N_EDGES];
__device__ int   g_part[SCAN_NB];
__device__ float g_pool[NG * HID];
__device__ int   g_pcnt[NG];

// ---------------------------------------------------------------------------
__global__ void k_zero() {
    int i = blockIdx.x * blockDim.x + threadIdx.x;
    if (i < N_NODES) g_cnt[i] = 0;
    if (i < NG * HID) g_pool[i] = 0.f;
    if (i < NG) g_pcnt[i] = 0;
}

// Embedding: h0 = concat(semb[x0], cemb[x1]) in fp16. 8 threads/node.
__global__ void k_embed(const int* __restrict__ x,
                        const int* __restrict__ batch,
                        const float* __restrict__ semb,
                        const float* __restrict__ cemb) {
    int t = blockIdx.x * blockDim.x + threadIdx.x;   // N_NODES*8
    int node = t >> 3, j = t & 7;
    const float4* src;
    if (j < 4) {
        int s = x[node * 2 + 0];
        src = (const float4*)&semb[s * 32 + j * 8];
    } else {
        int c = x[node * 2 + 1];
        src = (const float4*)&cemb[c * 32 + (j - 4) * 8];
    }
    float4 a = src[0], b = src[1];
    __half2 p0 = __floats2half2_rn(a.x, a.y);
    __half2 p1 = __floats2half2_rn(a.z, a.w);
    __half2 p2 = __floats2half2_rn(b.x, b.y);
    __half2 p3 = __floats2half2_rn(b.z, b.w);
    uint4 o = make_uint4(*(uint32_t*)&p0, *(uint32_t*)&p1,
                         *(uint32_t*)&p2, *(uint32_t*)&p3);
    *(uint4*)&g_h0[node * 64 + j * 8] = o;
    if (j == 0) atomicAdd(&g_pcnt[batch[node]], 1);
}

// Transpose weights to k-major fp16: wT[n][k] = w[k][n]
__global__ void k_prepw(const float* __restrict__ w0,
                        const float* __restrict__ w1,
                        const float* __restrict__ w2,
                        const float* __restrict__ w3) {
    int id = blockIdx.x * blockDim.x + threadIdx.x;   // 16384
    int m = id >> 12, r = id & 4095;
    int n = r >> 6, k = r & 63;
    const float* w = (m == 0) ? w0 : (m == 1) ? w1 : (m == 2) ? w2 : w3;
    g_wT[m * 4096 + n * 64 + k] = __float2half_rn(w[k * 64 + n]);
}

// In-degree histogram, 4 edges/thread via int4
__global__ void k_count(const int* __restrict__ ei) {
    int e = blockIdx.x * blockDim.x + threadIdx.x;
    if (e >= N_EDGES / 4) return;
    int4 t4 = ((const int4*)(ei + N_EDGES))[e];
    atomicAdd(&g_cnt[t4.x], 1);
    atomicAdd(&g_cnt[t4.y], 1);
    atomicAdd(&g_cnt[t4.z], 1);
    atomicAdd(&g_cnt[t4.w], 1);
}

__global__ void k_scan1() {
    __shared__ int s[SCAN_BS];
    int tid = threadIdx.x;
    int i = blockIdx.x * SCAN_BS + tid;
    int v = (i < N_NODES) ? g_cnt[i] : 0;
    s[tid] = v;
    __syncthreads();
    for (int off = 1; off < SCAN_BS; off <<= 1) {
        int t = (tid >= off) ? s[tid - off] : 0;
        __syncthreads();
        s[tid] += t;
        __syncthreads();
    }
    if (i < N_NODES) g_rowptr[i] = s[tid] - v;
    if (tid == SCAN_BS - 1) g_part[blockIdx.x] = s[tid];
}

__global__ void k_scan2() {
    int lane = threadIdx.x;
    int carry = 0;
    for (int base = 0; base < SCAN_NB; base += 32) {
        int idx = base + lane;
        int orig = (idx < SCAN_NB) ? g_part[idx] : 0;
        int v = orig;
        #pragma unroll
        for (int off = 1; off < 32; off <<= 1) {
            int t = __shfl_up_sync(0xffffffffu, v, off);
            if (lane >= off) v += t;
        }
        if (idx < SCAN_NB) g_part[idx] = carry + v - orig;
        carry += __shfl_sync(0xffffffffu, v, 31);
    }
}

__global__ void k_scan3() {
    int i = blockIdx.x * blockDim.x + threadIdx.x;
    if (i < N_NODES) {
        int r = g_rowptr[i] + g_part[i / SCAN_BS];
        g_rowptr[i] = r;
        g_cursor[i] = r;
    }
    if (i == 0) g_rowptr[N_NODES] = N_EDGES;
}

// Bucket edges by target, 4 edges/thread via int4
__global__ void k_bucket(const int* __restrict__ ei) {
    int e = blockIdx.x * blockDim.x + threadIdx.x;
    if (e >= N_EDGES / 4) return;
    int4 s4 = ((const int4*)ei)[e];
    int4 t4 = ((const int4*)(ei + N_EDGES))[e];
    int p0 = atomicAdd(&g_cursor[t4.x], 1);
    int p1 = atomicAdd(&g_cursor[t4.y], 1);
    int p2 = atomicAdd(&g_cursor[t4.z], 1);
    int p3 = atomicAdd(&g_cursor[t4.w], 1);
    g_eord[p0] = s4.x;
    g_eord[p1] = s4.y;
    g_eord[p2] = s4.z;
    g_eord[p3] = s4.w;
}

// ---------------------------------------------------------------------------
// CSR gather (fp16): agg[n] = mean_{s in N(n)} h[s]. One warp/node,
// 4-way unrolled neighbor loop (4 independent 128B row loads in flight).
// fp32 accumulation.
__global__ void __launch_bounds__(256) k_gather(int layer) {
    int w = (blockIdx.x * blockDim.x + threadIdx.x) >> 5;
    int lane = threadIdx.x & 31;
    if (w >= N_NODES) return;
    int start = g_rowptr[w], end = g_rowptr[w + 1];
    const __half* __restrict__ h = layer ? g_h1 : g_h0;
    float2 acc = make_float2(0.f, 0.f);
    for (int base = start; base < end; base += 32) {
        int p = base + lane;
        int idx = (p < end) ? g_eord[p] : 0;
        int m = min(32, end - base);
        int j = 0;
        for (; j + 4 <= m; j += 4) {
            int s0 = __shfl_sync(0xffffffffu, idx, j);
            int s1 = __shfl_sync(0xffffffffu, idx, j + 1);
            int s2 = __shfl_sync(0xffffffffu, idx, j + 2);
            int s3 = __shfl_sync(0xffffffffu, idx, j + 3);
            __half2 v0 = *(const __half2*)&h[(size_t)s0 * 64 + lane * 2];
            __half2 v1 = *(const __half2*)&h[(size_t)s1 * 64 + lane * 2];
            __half2 v2 = *(const __half2*)&h[(size_t)s2 * 64 + lane * 2];
            __half2 v3 = *(const __half2*)&h[(size_t)s3 * 64 + lane * 2];
            float2 f0 = __half22float2(v0);
            float2 f1 = __half22float2(v1);
            float2 f2 = __half22float2(v2);
            float2 f3 = __half22float2(v3);
            acc.x += (f0.x + f1.x) + (f2.x + f3.x);
            acc.y += (f0.y + f1.y) + (f2.y + f3.y);
        }
        for (; j < m; j++) {
            int s = __shfl_sync(0xffffffffu, idx, j);
            float2 f = __half22float2(
                *(const __half2*)&h[(size_t)s * 64 + lane * 2]);
            acc.x += f.x;
            acc.y += f.y;
        }
    }
    float inv = 1.f / (float)max(end - start, 1);
    acc.x *= inv; acc.y *= inv;
    __half2 o = __floats2half2_rn(acc.x, acc.y);
    *(__half2*)&g_agg[w * 64 + lane * 2] = o;
}

// ---------------------------------------------------------------------------
// HMMA node update: out = relu(agg @ wl + h @ wr + b)
// mma.sync.m16n8k16 f16 -> f32. 256 threads = 8 warps, 128 nodes/block.
// A and B fragments loaded directly from gmem (k-major, contiguous b32 per
// fragment register). No smem tiles.
__global__ void __launch_bounds__(256) k_upd(const float* __restrict__ bias,
                                             const int* __restrict__ batch,
                                             int layer) {
    __shared__ float sbias[64];
    int tid = threadIdx.x;
    int wid = tid >> 5, lane = tid & 31;
    if (tid < 64) sbias[tid] = bias[tid];
    __syncthreads();

    int m0 = blockIdx.x * 128 + wid * 16;
    int qp = (lane & 3) * 2;       // k-pair offset within 16
    int gi = lane >> 2;            // group index 0..7
    int r0 = m0 + gi;
    int r1 = r0 + 8;
    bool v0 = r0 < N_NODES, v1 = r1 < N_NODES;

    float acc[8][4];
    #pragma unroll
    for (int t = 0; t < 8; t++)
        #pragma unroll
        for (int i = 0; i < 4; i++) acc[t][i] = 0.f;

    const __half* __restrict__ hin = layer ? g_h1 : g_h0;

    #pragma unroll
    for (int kc = 0; kc < 2; kc++) {
        const __half* __restrict__ X = kc ? hin : g_agg;
        const __half* __restrict__ W = &g_wT[(layer * 2 + kc) * 4096];
        #pragma unroll
        for (int ks = 0; ks < 4; ks++) {
            int kb = ks * 16;
            uint32_t a0 = 0, a1 = 0, a2 = 0, a3 = 0;
            if (v0) {
                a0 = *(const uint32_t*)&X[(size_t)r0 * 64 + kb + qp];
                a2 = *(const uint32_t*)&X[(size_t)r0 * 64 + kb + qp + 8];
            }
            if (v1) {
                a1 = *(const uint32_t*)&X[(size_t)r1 * 64 + kb + qp];
                a3 = *(const uint32_t*)&X[(size_t)r1 * 64 + kb + qp + 8];
            }
            #pragma unroll
            for (int t = 0; t < 8; t++) {
                int n = t * 8 + gi;
                uint32_t b0 = *(const uint32_t*)&W[n * 64 + kb + qp];
                uint32_t b1 = *(const uint32_t*)&W[n * 64 + kb + qp + 8];
                asm volatile(
                    "mma.sync.aligned.m16n8k16.row.col.f32.f16.f16.f32 "
                    "{%0,%1,%2,%3}, {%4,%5,%6,%7}, {%8,%9}, {%0,%1,%2,%3};"
                    : "+f"(acc[t][0]), "+f"(acc[t][1]),
                      "+f"(acc[t][2]), "+f"(acc[t][3])
                    : "r"(a0), "r"(a1), "r"(a2), "r"(a3), "r"(b0), "r"(b1));
            }
        }
    }

    // epilogue: bias + relu, then store (layer 0) or pool (layer 1)
    int b0g = v0 ? batch[r0] : 0;
    int b1g = v1 ? batch[r1] : 0;
    #pragma unroll
    for (int t = 0; t < 8; t++) {
        int ct = t * 8 + qp;
        float bx = sbias[ct], by = sbias[ct + 1];
        float o0 = fmaxf(acc[t][0] + bx, 0.f);
        float o1 = fmaxf(acc[t][1] + by, 0.f);
        float o2 = fmaxf(acc[t][2] + bx, 0.f);
        float o3 = fmaxf(acc[t][3] + by, 0.f);
        if (layer == 0) {
            if (v0) {
                __half2 p = __floats2half2_rn(o0, o1);
                *(__half2*)&g_h1[(size_t)r0 * 64 + ct] = p;
            }
            if (v1) {
                __half2 p = __floats2half2_rn(o2, o3);
                *(__half2*)&g_h1[(size_t)r1 * 64 + ct] = p;
            }
        } else {
            if (v0) atomicAdd((float2*)&g_pool[b0g * 64 + ct],
                              make_float2(o0, o1));
            if (v1) atomicAdd((float2*)&g_pool[b1g * 64 + ct],
                              make_float2(o2, o3));
        }
    }
}

// ---------------------------------------------------------------------------
__global__ void k_final(const float* __restrict__ wc,
                        const float* __restrict__ bc,
                        float* __restrict__ out) {
    int g = blockIdx.x * blockDim.x + threadIdx.x;
    if (g >= NG) return;
    float inv = 1.f / fmaxf((float)g_pcnt[g], 1.f);
    float acc[NCLS];
    #pragma unroll
    for (int c = 0; c < NCLS; c++) acc[c] = bc[c];
    for (int k = 0; k < 64; k++) {
        float p = g_pool[g * 64 + k] * inv;
        #pragma unroll
        for (int c = 0; c < NCLS; c++)
            acc[c] += p * wc[k * NCLS + c];
    }
    #pragma unroll
    for (int c = 0; c < NCLS; c++) out[g * NCLS + c] = acc[c];
}

// ---------------------------------------------------------------------------
extern "C" void kernel_launch(void* const* d_in, const int* in_sizes, int n_in,
                              void* d_out, int out_size) {
    int o = (n_in >= 14) ? 1 : 0;
    const int*   x     = (const int*)d_in[0];
    const int*   ei    = (const int*)d_in[1];
    const int*   batch = (const int*)d_in[2];
    const float* semb  = (const float*)d_in[3 + o];
    const float* cemb  = (const float*)d_in[4 + o];
    const float* w1l   = (const float*)d_in[5 + o];
    const float* w1r   = (const float*)d_in[6 + o];
    const float* b1    = (const float*)d_in[7 + o];
    const float* w2l   = (const float*)d_in[8 + o];
    const float* w2r   = (const float*)d_in[9 + o];
    const float* b2    = (const float*)d_in[10 + o];
    const float* wc    = (const float*)d_in[11 + o];
    const float* bc    = (const float*)d_in[12 + o];
    float* out = (float*)d_out;

    k_zero<<<(N_NODES + 255) / 256, 256>>>();
    k_embed<<<(N_NODES * 8) / 256, 256>>>(x, batch, semb, cemb);
    k_prepw<<<64, 256>>>(w1l, w1r, w2l, w2r);
    // CSR build (shared by both layers)
    k_count<<<(N_EDGES / 4 + 255) / 256, 256>>>(ei);
    k_scan1<<<SCAN_NB, SCAN_BS>>>();
    k_scan2<<<1, 32>>>();
    k_scan3<<<(N_NODES + 255) / 256, 256>>>();
    k_bucket<<<(N_EDGES / 4 + 255) / 256, 256>>>(ei);
    // layer 1
    k_gather<<<(N_NODES * 32 + 255) / 256, 256>>>(0);
    k_upd<<<(N_NODES + 127) / 128, 256>>>(b1, batch, 0);
    // layer 2
    k_gather<<<(N_NODES * 32 + 255) / 256, 256>>>(1);
    k_upd<<<(N_NODES + 127) / 128, 256>>>(b2, batch, 1);
    // pool -> classifier
    k_final<<<(NG + 255) / 256, 256>>>(wc, bc, out);
}

// round 9
// speedup vs baseline: 1.1366x; 1.0496x over previous
#include <cuda_runtime.h>
#include <cuda_fp16.h>
#include <cstdint>

#define N_NODES 100000
#define N_EDGES 1600000
#define HID 64
#define NG 512
#define NCLS 10
#define SCAN_BS 512
#define SCAN_NB ((N_NODES + SCAN_BS - 1) / SCAN_BS)   // 196

// ---------------- device scratch (no allocations allowed) -------------------
__device__ __half g_h0[N_NODES * HID];
__device__ __half g_h1[N_NODES * HID];
__device__ __half g_agg[N_NODES * HID];
__device__ __half g_wT[4 * 4096];   // wT[m][n*64+k] = w[k][n], fp16
__device__ int   g_cnt[N_NODES];
__device__ int   g_rowptr[N_NODES + 1];
__device__ int   g_cursor[N_NODES];
__device__ int   g_eord[N_EDGES];
__device__ int   g_part[SCAN_NB];
__device__ float g_pool[NG * HID];
__device__ int   g_pcnt[NG];

// ---------------------------------------------------------------------------
__global__ void k_zero() {
    int i = blockIdx.x * blockDim.x + threadIdx.x;
    if (i < N_NODES) g_cnt[i] = 0;
    if (i < NG * HID) g_pool[i] = 0.f;
    if (i < NG) g_pcnt[i] = 0;
}

// Embedding: h0 = concat(semb[x0], cemb[x1]) in fp16. 8 threads/node.
__global__ void k_embed(const int* __restrict__ x,
                        const int* __restrict__ batch,
                        const float* __restrict__ semb,
                        const float* __restrict__ cemb) {
    int t = blockIdx.x * blockDim.x + threadIdx.x;   // N_NODES*8
    int node = t >> 3, j = t & 7;
    const float4* src;
    if (j < 4) {
        int s = x[node * 2 + 0];
        src = (const float4*)&semb[s * 32 + j * 8];
    } else {
        int c = x[node * 2 + 1];
        src = (const float4*)&cemb[c * 32 + (j - 4) * 8];
    }
    float4 a = src[0], b = src[1];
    __half2 p0 = __floats2half2_rn(a.x, a.y);
    __half2 p1 = __floats2half2_rn(a.z, a.w);
    __half2 p2 = __floats2half2_rn(b.x, b.y);
    __half2 p3 = __floats2half2_rn(b.z, b.w);
    uint4 o = make_uint4(*(uint32_t*)&p0, *(uint32_t*)&p1,
                         *(uint32_t*)&p2, *(uint32_t*)&p3);
    *(uint4*)&g_h0[node * 64 + j * 8] = o;
    if (j == 0) atomicAdd(&g_pcnt[batch[node]], 1);
}

// Transpose weights to k-major fp16: wT[n][k] = w[k][n]
__global__ void k_prepw(const float* __restrict__ w0,
                        const float* __restrict__ w1,
                        const float* __restrict__ w2,
                        const float* __restrict__ w3) {
    int id = blockIdx.x * blockDim.x + threadIdx.x;   // 16384
    int m = id >> 12, r = id & 4095;
    int n = r >> 6, k = r & 63;
    const float* w = (m == 0) ? w0 : (m == 1) ? w1 : (m == 2) ? w2 : w3;
    g_wT[m * 4096 + n * 64 + k] = __float2half_rn(w[k * 64 + n]);
}

// In-degree histogram (scalar — atomic-bound, vectorizing proven neutral)
__global__ void k_count(const int* __restrict__ ei) {
    int e = blockIdx.x * blockDim.x + threadIdx.x;
    atomicAdd(&g_cnt[ei[N_EDGES + e]], 1);
}

__global__ void k_scan1() {
    __shared__ int s[SCAN_BS];
    int tid = threadIdx.x;
    int i = blockIdx.x * SCAN_BS + tid;
    int v = (i < N_NODES) ? g_cnt[i] : 0;
    s[tid] = v;
    __syncthreads();
    for (int off = 1; off < SCAN_BS; off <<= 1) {
        int t = (tid >= off) ? s[tid - off] : 0;
        __syncthreads();
        s[tid] += t;
        __syncthreads();
    }
    if (i < N_NODES) g_rowptr[i] = s[tid] - v;
    if (tid == SCAN_BS - 1) g_part[blockIdx.x] = s[tid];
}

__global__ void k_scan2() {
    int lane = threadIdx.x;
    int carry = 0;
    for (int base = 0; base < SCAN_NB; base += 32) {
        int idx = base + lane;
        int orig = (idx < SCAN_NB) ? g_part[idx] : 0;
        int v = orig;
        #pragma unroll
        for (int off = 1; off < 32; off <<= 1) {
            int t = __shfl_up_sync(0xffffffffu, v, off);
            if (lane >= off) v += t;
        }
        if (idx < SCAN_NB) g_part[idx] = carry + v - orig;
        carry += __shfl_sync(0xffffffffu, v, 31);
    }
}

__global__ void k_scan3() {
    int i = blockIdx.x * blockDim.x + threadIdx.x;
    if (i < N_NODES) {
        int r = g_rowptr[i] + g_part[i / SCAN_BS];
        g_rowptr[i] = r;
        g_cursor[i] = r;
    }
    if (i == 0) g_rowptr[N_NODES] = N_EDGES;
}

// Bucket edges by target (scalar)
__global__ void k_bucket(const int* __restrict__ ei) {
    int e = blockIdx.x * blockDim.x + threadIdx.x;
    int tgt = ei[N_EDGES + e];
    int pos = atomicAdd(&g_cursor[tgt], 1);
    g_eord[pos] = ei[e];
}

// ---------------------------------------------------------------------------
// CSR gather (fp16): agg[n] = mean_{s in N(n)} h[s]. One warp/node.
// Warp split as 4 edge-subgroups x 8 dim-lanes: one LDG.128 loads 16B of one
// edge's row -> 4 edges per load instruction across the warp. fp32 accum,
// xor-reduce across edge subgroups at the end.
__global__ void __launch_bounds__(256) k_gather(int layer) {
    int w = (blockIdx.x * blockDim.x + threadIdx.x) >> 5;
    int lane = threadIdx.x & 31;
    if (w >= N_NODES) return;
    int start = g_rowptr[w], end = g_rowptr[w + 1];
    int deg = end - start;
    const __half* __restrict__ h = layer ? g_h1 : g_h0;
    int eg = lane >> 3;        // edge subgroup 0..3
    int dg = lane & 7;         // dim group: halves [dg*8, dg*8+8)

    float acc[8];
    #pragma unroll
    for (int i = 0; i < 8; i++) acc[i] = 0.f;

    for (int base = start; base < end; base += 32) {
        int p = base + lane;
        int idx = (p < end) ? g_eord[p] : 0;
        int m = min(32, end - base);
        int fullc = m >> 2;     // chunks of 4 edges with no bounds check
        int c = 0;
        #pragma unroll 4
        for (; c < fullc; c++) {
            int s = __shfl_sync(0xffffffffu, idx, c * 4 + eg);
            uint4 v = *(const uint4*)&h[(size_t)s * 64 + dg * 8];
            __half2* hv = (__half2*)&v;
            #pragma unroll
            for (int q = 0; q < 4; q++) {
                float2 f = __half22float2(hv[q]);
                acc[q * 2]     += f.x;
                acc[q * 2 + 1] += f.y;
            }
        }
        if (c * 4 < m) {        // remainder chunk (1-3 edges)
            int j = c * 4 + eg;
            int s = __shfl_sync(0xffffffffu, idx, j);
            uint4 v = *(const uint4*)&h[(size_t)s * 64 + dg * 8];
            if (j < m) {
                __half2* hv = (__half2*)&v;
                #pragma unroll
                for (int q = 0; q < 4; q++) {
                    float2 f = __half22float2(hv[q]);
                    acc[q * 2]     += f.x;
                    acc[q * 2 + 1] += f.y;
                }
            }
        }
    }

    // reduce across edge subgroups (lane bits 3 and 4)
    #pragma unroll
    for (int i = 0; i < 8; i++) {
        acc[i] += __shfl_xor_sync(0xffffffffu, acc[i], 8);
        acc[i] += __shfl_xor_sync(0xffffffffu, acc[i], 16);
    }
    if (lane < 8) {
        float inv = 1.f / (float)max(deg, 1);
        __half2 o[4];
        #pragma unroll
        for (int q = 0; q < 4; q++)
            o[q] = __floats2half2_rn(acc[q * 2] * inv, acc[q * 2 + 1] * inv);
        *(uint4*)&g_agg[(size_t)w * 64 + dg * 8] = *(uint4*)o;
    }
}

// ---------------------------------------------------------------------------
// HMMA node update: out = relu(agg @ wl + h @ wr + b)
// mma.sync.m16n8k16 f16 -> f32. 256 threads = 8 warps, 128 nodes/block.
__global__ void __launch_bounds__(256) k_upd(const float* __restrict__ bias,
                                             const int* __restrict__ batch,
                                             int layer) {
    __shared__ float sbias[64];
    int tid = threadIdx.x;
    int wid = tid >> 5, lane = tid & 31;
    if (tid < 64) sbias[tid] = bias[tid];
    __syncthreads();

    int m0 = blockIdx.x * 128 + wid * 16;
    int qp = (lane & 3) * 2;       // k-pair offset within 16
    int gi = lane >> 2;            // group index 0..7
    int r0 = m0 + gi;
    int r1 = r0 + 8;
    bool v0 = r0 < N_NODES, v1 = r1 < N_NODES;

    float acc[8][4];
    #pragma unroll
    for (int t = 0; t < 8; t++)
        #pragma unroll
        for (int i = 0; i < 4; i++) acc[t][i] = 0.f;

    const __half* __restrict__ hin = layer ? g_h1 : g_h0;

    #pragma unroll
    for (int kc = 0; kc < 2; kc++) {
        const __half* __restrict__ X = kc ? hin : g_agg;
        const __half* __restrict__ W = &g_wT[(layer * 2 + kc) * 4096];
        #pragma unroll
        for (int ks = 0; ks < 4; ks++) {
            int kb = ks * 16;
            uint32_t a0 = 0, a1 = 0, a2 = 0, a3 = 0;
            if (v0) {
                a0 = *(const uint32_t*)&X[(size_t)r0 * 64 + kb + qp];
                a2 = *(const uint32_t*)&X[(size_t)r0 * 64 + kb + qp + 8];
            }
            if (v1) {
                a1 = *(const uint32_t*)&X[(size_t)r1 * 64 + kb + qp];
                a3 = *(const uint32_t*)&X[(size_t)r1 * 64 + kb + qp + 8];
            }
            #pragma unroll
            for (int t = 0; t < 8; t++) {
                int n = t * 8 + gi;
                uint32_t b0 = *(const uint32_t*)&W[n * 64 + kb + qp];
                uint32_t b1 = *(const uint32_t*)&W[n * 64 + kb + qp + 8];
                asm volatile(
                    "mma.sync.aligned.m16n8k16.row.col.f32.f16.f16.f32 "
                    "{%0,%1,%2,%3}, {%4,%5,%6,%7}, {%8,%9}, {%0,%1,%2,%3};"
                    : "+f"(acc[t][0]), "+f"(acc[t][1]),
                      "+f"(acc[t][2]), "+f"(acc[t][3])
                    : "r"(a0), "r"(a1), "r"(a2), "r"(a3), "r"(b0), "r"(b1));
            }
        }
    }

    // epilogue: bias + relu, then store (layer 0) or pool (layer 1)
    int b0g = v0 ? batch[r0] : 0;
    int b1g = v1 ? batch[r1] : 0;
    #pragma unroll
    for (int t = 0; t < 8; t++) {
        int ct = t * 8 + qp;
        float bx = sbias[ct], by = sbias[ct + 1];
        float o0 = fmaxf(acc[t][0] + bx, 0.f);
        float o1 = fmaxf(acc[t][1] + by, 0.f);
        float o2 = fmaxf(acc[t][2] + bx, 0.f);
        float o3 = fmaxf(acc[t][3] + by, 0.f);
        if (layer == 0) {
            if (v0) {
                __half2 p = __floats2half2_rn(o0, o1);
                *(__half2*)&g_h1[(size_t)r0 * 64 + ct] = p;
            }
            if (v1) {
                __half2 p = __floats2half2_rn(o2, o3);
                *(__half2*)&g_h1[(size_t)r1 * 64 + ct] = p;
            }
        } else {
            if (v0) atomicAdd((float2*)&g_pool[b0g * 64 + ct],
                              make_float2(o0, o1));
            if (v1) atomicAdd((float2*)&g_pool[b1g * 64 + ct],
                              make_float2(o2, o3));
        }
    }
}

// ---------------------------------------------------------------------------
__global__ void k_final(const float* __restrict__ wc,
                        const float* __restrict__ bc,
                        float* __restrict__ out) {
    int g = blockIdx.x * blockDim.x + threadIdx.x;
    if (g >= NG) return;
    float inv = 1.f / fmaxf((float)g_pcnt[g], 1.f);
    float acc[NCLS];
    #pragma unroll
    for (int c = 0; c < NCLS; c++) acc[c] = bc[c];
    for (int k = 0; k < 64; k++) {
        float p = g_pool[g * 64 + k] * inv;
        #pragma unroll
        for (int c = 0; c < NCLS; c++)
            acc[c] += p * wc[k * NCLS + c];
    }
    #pragma unroll
    for (int c = 0; c < NCLS; c++) out[g * NCLS + c] = acc[c];
}

// ---------------------------------------------------------------------------
extern "C" void kernel_launch(void* const* d_in, const int* in_sizes, int n_in,
                              void* d_out, int out_size) {
    int o = (n_in >= 14) ? 1 : 0;
    const int*   x     = (const int*)d_in[0];
    const int*   ei    = (const int*)d_in[1];
    const int*   batch = (const int*)d_in[2];
    const float* semb  = (const float*)d_in[3 + o];
    const float* cemb  = (const float*)d_in[4 + o];
    const float* w1l   = (const float*)d_in[5 + o];
    const float* w1r   = (const float*)d_in[6 + o];
    const float* b1    = (const float*)d_in[7 + o];
    const float* w2l   = (const float*)d_in[8 + o];
    const float* w2r   = (const float*)d_in[9 + o];
    const float* b2    = (const float*)d_in[10 + o];
    const float* wc    = (const float*)d_in[11 + o];
    const float* bc    = (const float*)d_in[12 + o];
    float* out = (float*)d_out;

    k_zero<<<(N_NODES + 255) / 256, 256>>>();
    k_embed<<<(N_NODES * 8) / 256, 256>>>(x, batch, semb, cemb);
    k_prepw<<<64, 256>>>(w1l, w1r, w2l, w2r);
    // CSR build (shared by both layers)
    k_count<<<N_EDGES / 256, 256>>>(ei);
    k_scan1<<<SCAN_NB, SCAN_BS>>>();
    k_scan2<<<1, 32>>>();
    k_scan3<<<(N_NODES + 255) / 256, 256>>>();
    k_bucket<<<N_EDGES / 256, 256>>>(ei);
    // layer 1
    k_gather<<<(N_NODES * 32 + 255) / 256, 256>>>(0);
    k_upd<<<(N_NODES + 127) / 128, 256>>>(b1, batch, 0);
    // layer 2
    k_gather<<<(N_NODES * 32 + 255) / 256, 256>>>(1);
    k_upd<<<(N_NODES + 127) / 128, 256>>>(b2, batch, 1);
    // pool -> classifier
    k_final<<<(NG + 255) / 256, 256>>>(wc, bc, out);
}

// round 10
// speedup vs baseline: 1.2840x; 1.1296x over previous
#include <cuda_runtime.h>
#include <cuda_fp16.h>
#include <cstdint>

#define N_NODES 100000
#define N_EDGES 1600000
#define HID 64
#define NG 512
#define NCLS 10
#define NCODE 1024          // 64 shapes x 16 colors
#define SCAN_BS 512
#define SCAN_NB ((N_NODES + SCAN_BS - 1) / SCAN_BS)   // 196

// ---------------- device scratch (no allocations allowed) -------------------
__device__ __half g_h1[N_NODES * HID];
__device__ __half g_agg[N_NODES * HID];
__device__ __half g_wT[4 * 4096];   // wT[m][n*64+k] = w[k][n], fp16 (m=2,3 used)
__device__ __align__(16) __half g_y[NCODE * HID];    // 128 KB: code -> h0@w1l (fp16)
__device__ float  g_z2[NCODE * HID];                 // 256 KB: code -> h0@w1r + b1
__device__ int   g_code[N_NODES];
__device__ int   g_cnt[N_NODES];
__device__ int   g_rowptr[N_NODES + 1];
__device__ int   g_cursor[N_NODES];
__device__ int   g_eord[N_EDGES];
__device__ int   g_ecode[N_EDGES];
__device__ int   g_part[SCAN_NB];
__device__ float g_pool[NG * HID];
__device__ int   g_pcnt[NG];

// ---------------------------------------------------------------------------
__global__ void k_zero() {
    int i = blockIdx.x * blockDim.x + threadIdx.x;
    if (i < N_NODES) g_cnt[i] = 0;
    if (i < NG * HID) g_pool[i] = 0.f;
    if (i < NG) g_pcnt[i] = 0;
}

// Per-node code + per-graph node counts
__global__ void k_code(const int* __restrict__ x,
                       const int* __restrict__ batch) {
    int n = blockIdx.x * blockDim.x + threadIdx.x;
    if (n >= N_NODES) return;
    g_code[n] = x[n * 2] * 16 + x[n * 2 + 1];
    atomicAdd(&g_pcnt[batch[n]], 1);
}

// Build code tables: y[code] = h0(code) @ w1l (fp16), z2[code] = h0@w1r + b1 (fp32)
// 8192 threads: (code, jg) with jg covering 8 output cols.
__global__ void k_tab(const float* __restrict__ semb,
                      const float* __restrict__ cemb,
                      const float* __restrict__ w1l,
                      const float* __restrict__ w1r,
                      const float* __restrict__ b1) {
    int id = blockIdx.x * blockDim.x + threadIdx.x;
    if (id >= NCODE * 8) return;
    int code = id >> 3, jg = id & 7;
    int s = code >> 4, c = code & 15;
    float oy[8], oz[8];
    #pragma unroll
    for (int j = 0; j < 8; j++) { oy[j] = 0.f; oz[j] = 0.f; }
    for (int k = 0; k < 32; k++) {
        float a = semb[s * 32 + k];
        #pragma unroll
        for (int j = 0; j < 8; j++) {
            oy[j] += a * w1l[k * 64 + jg * 8 + j];
            oz[j] += a * w1r[k * 64 + jg * 8 + j];
        }
    }
    for (int k = 0; k < 32; k++) {
        float a = cemb[c * 32 + k];
        #pragma unroll
        for (int j = 0; j < 8; j++) {
            oy[j] += a * w1l[(32 + k) * 64 + jg * 8 + j];
            oz[j] += a * w1r[(32 + k) * 64 + jg * 8 + j];
        }
    }
    __half2 yh[4];
    #pragma unroll
    for (int q = 0; q < 4; q++)
        yh[q] = __floats2half2_rn(oy[q * 2], oy[q * 2 + 1]);
    *(uint4*)&g_y[code * 64 + jg * 8] = *(uint4*)yh;
    #pragma unroll
    for (int j = 0; j < 8; j++)
        g_z2[code * 64 + jg * 8 + j] = oz[j] + b1[jg * 8 + j];
}

// Transpose weights to k-major fp16: wT[n][k] = w[k][n] (slots 2,3: w2l,w2r)
__global__ void k_prepw(const float* __restrict__ w0,
                        const float* __restrict__ w1,
                        const float* __restrict__ w2,
                        const float* __restrict__ w3) {
    int id = blockIdx.x * blockDim.x + threadIdx.x;   // 16384
    int m = id >> 12, r = id & 4095;
    int n = r >> 6, k = r & 63;
    const float* w = (m == 0) ? w0 : (m == 1) ? w1 : (m == 2) ? w2 : w3;
    g_wT[m * 4096 + n * 64 + k] = __float2half_rn(w[k * 64 + n]);
}

// In-degree histogram
__global__ void k_count(const int* __restrict__ ei) {
    int e = blockIdx.x * blockDim.x + threadIdx.x;
    atomicAdd(&g_cnt[ei[N_EDGES + e]], 1);
}

__global__ void k_scan1() {
    __shared__ int s[SCAN_BS];
    int tid = threadIdx.x;
    int i = blockIdx.x * SCAN_BS + tid;
    int v = (i < N_NODES) ? g_cnt[i] : 0;
    s[tid] = v;
    __syncthreads();
    for (int off = 1; off < SCAN_BS; off <<= 1) {
        int t = (tid >= off) ? s[tid - off] : 0;
        __syncthreads();
        s[tid] += t;
        __syncthreads();
    }
    if (i < N_NODES) g_rowptr[i] = s[tid] - v;
    if (tid == SCAN_BS - 1) g_part[blockIdx.x] = s[tid];
}

__global__ void k_scan2() {
    int lane = threadIdx.x;
    int carry = 0;
    for (int base = 0; base < SCAN_NB; base += 32) {
        int idx = base + lane;
        int orig = (idx < SCAN_NB) ? g_part[idx] : 0;
        int v = orig;
        #pragma unroll
        for (int off = 1; off < 32; off <<= 1) {
            int t = __shfl_up_sync(0xffffffffu, v, off);
            if (lane >= off) v += t;
        }
        if (idx < SCAN_NB) g_part[idx] = carry + v - orig;
        carry += __shfl_sync(0xffffffffu, v, 31);
    }
}

__global__ void k_scan3() {
    int i = blockIdx.x * blockDim.x + threadIdx.x;
    if (i < N_NODES) {
        int r = g_rowptr[i] + g_part[i / SCAN_BS];
        g_rowptr[i] = r;
        g_cursor[i] = r;
    }
    if (i == 0) g_rowptr[N_NODES] = N_EDGES;
}

// Bucket edges by target; also emit source codes in CSR order
__global__ void k_bucket(const int* __restrict__ ei) {
    int e = blockIdx.x * blockDim.x + threadIdx.x;
    int src = ei[e];
    int tgt = ei[N_EDGES + e];
    int pos = atomicAdd(&g_cursor[tgt], 1);
    g_eord[pos] = src;
    g_ecode[pos] = g_code[src];
}

// ---------------------------------------------------------------------------
// Layer 1 (fully fused, table-based):
// h1[n] = relu( mean_{src in N(n)} y[code[src]] + z2[code[n]] )
// One warp/node, 4 edge-subgroups x 8 dim-lanes; y rows are L1-resident
// (128 KB table). fp32 accumulation.
__global__ void __launch_bounds__(256) k_l1(void) {
    int w = (blockIdx.x * blockDim.x + threadIdx.x) >> 5;
    int lane = threadIdx.x & 31;
    if (w >= N_NODES) return;
    int start = g_rowptr[w], end = g_rowptr[w + 1];
    int deg = end - start;
    int eg = lane >> 3;        // edge subgroup 0..3
    int dg = lane & 7;         // dim group: halves [dg*8, dg*8+8)

    float acc[8];
    #pragma unroll
    for (int i = 0; i < 8; i++) acc[i] = 0.f;

    for (int base = start; base < end; base += 32) {
        int p = base + lane;
        int ec = (p < end) ? g_ecode[p] : 0;
        int m = min(32, end - base);
        int fullc = m >> 2;
        int c = 0;
        #pragma unroll 4
        for (; c < fullc; c++) {
            int code = __shfl_sync(0xffffffffu, ec, c * 4 + eg);
            uint4 v = *(const uint4*)&g_y[code * 64 + dg * 8];
            __half2* hv = (__half2*)&v;
            #pragma unroll
            for (int q = 0; q < 4; q++) {
                float2 f = __half22float2(hv[q]);
                acc[q * 2]     += f.x;
                acc[q * 2 + 1] += f.y;
            }
        }
        if (c * 4 < m) {
            int j = c * 4 + eg;
            int code = __shfl_sync(0xffffffffu, ec, j);
            uint4 v = *(const uint4*)&g_y[code * 64 + dg * 8];
            if (j < m) {
                __half2* hv = (__half2*)&v;
                #pragma unroll
                for (int q = 0; q < 4; q++) {
                    float2 f = __half22float2(hv[q]);
                    acc[q * 2]     += f.x;
                    acc[q * 2 + 1] += f.y;
                }
            }
        }
    }

    #pragma unroll
    for (int i = 0; i < 8; i++) {
        acc[i] += __shfl_xor_sync(0xffffffffu, acc[i], 8);
        acc[i] += __shfl_xor_sync(0xffffffffu, acc[i], 16);
    }
    if (lane < 8) {
        float inv = 1.f / (float)max(deg, 1);
        int cn = g_code[w];
        float4 z0 = *(const float4*)&g_z2[cn * 64 + dg * 8];
        float4 z1 = *(const float4*)&g_z2[cn * 64 + dg * 8 + 4];
        float o[8];
        o[0] = fmaxf(acc[0] * inv + z0.x, 0.f);
        o[1] = fmaxf(acc[1] * inv + z0.y, 0.f);
        o[2] = fmaxf(acc[2] * inv + z0.z, 0.f);
        o[3] = fmaxf(acc[3] * inv + z0.w, 0.f);
        o[4] = fmaxf(acc[4] * inv + z1.x, 0.f);
        o[5] = fmaxf(acc[5] * inv + z1.y, 0.f);
        o[6] = fmaxf(acc[6] * inv + z1.z, 0.f);
        o[7] = fmaxf(acc[7] * inv + z1.w, 0.f);
        __half2 oh[4];
        #pragma unroll
        for (int q = 0; q < 4; q++)
            oh[q] = __floats2half2_rn(o[q * 2], o[q * 2 + 1]);
        *(uint4*)&g_h1[(size_t)w * 64 + dg * 8] = *(uint4*)oh;
    }
}

// ---------------------------------------------------------------------------
// Layer-2 CSR gather (fp16): agg[n] = mean_{s in N(n)} h1[s]. One warp/node,
// 4 edge-subgroups x 8 dim-lanes, LDG.128. fp32 accum.
__global__ void __launch_bounds__(256) k_gather(void) {
    int w = (blockIdx.x * blockDim.x + threadIdx.x) >> 5;
    int lane = threadIdx.x & 31;
    if (w >= N_NODES) return;
    int start = g_rowptr[w], end = g_rowptr[w + 1];
    int deg = end - start;
    const __half* __restrict__ h = g_h1;
    int eg = lane >> 3;
    int dg = lane & 7;

    float acc[8];
    #pragma unroll
    for (int i = 0; i < 8; i++) acc[i] = 0.f;

    for (int base = start; base < end; base += 32) {
        int p = base + lane;
        int idx = (p < end) ? g_eord[p] : 0;
        int m = min(32, end - base);
        int fullc = m >> 2;
        int c = 0;
        #pragma unroll 4
        for (; c < fullc; c++) {
            int s = __shfl_sync(0xffffffffu, idx, c * 4 + eg);
            uint4 v = *(const uint4*)&h[(size_t)s * 64 + dg * 8];
            __half2* hv = (__half2*)&v;
            #pragma unroll
            for (int q = 0; q < 4; q++) {
                float2 f = __half22float2(hv[q]);
                acc[q * 2]     += f.x;
                acc[q * 2 + 1] += f.y;
            }
        }
        if (c * 4 < m) {
            int j = c * 4 + eg;
            int s = __shfl_sync(0xffffffffu, idx, j);
            uint4 v = *(const uint4*)&h[(size_t)s * 64 + dg * 8];
            if (j < m) {
                __half2* hv = (__half2*)&v;
                #pragma unroll
                for (int q = 0; q < 4; q++) {
                    float2 f = __half22float2(hv[q]);
                    acc[q * 2]     += f.x;
                    acc[q * 2 + 1] += f.y;
                }
            }
        }
    }

    #pragma unroll
    for (int i = 0; i < 8; i++) {
        acc[i] += __shfl_xor_sync(0xffffffffu, acc[i], 8);
        acc[i] += __shfl_xor_sync(0xffffffffu, acc[i], 16);
    }
    if (lane < 8) {
        float inv = 1.f / (float)max(deg, 1);
        __half2 o[4];
        #pragma unroll
        for (int q = 0; q < 4; q++)
            o[q] = __floats2half2_rn(acc[q * 2] * inv, acc[q * 2 + 1] * inv);
        *(uint4*)&g_agg[(size_t)w * 64 + dg * 8] = *(uint4*)o;
    }
}

// ---------------------------------------------------------------------------
// Layer-2 HMMA update + pool: pool[batch[n]] += relu(agg @ w2l + h1 @ w2r + b2)
// mma.sync.m16n8k16 f16 -> f32. 256 threads = 8 warps, 128 nodes/block.
__global__ void __launch_bounds__(256) k_upd(const float* __restrict__ bias,
                                             const int* __restrict__ batch) {
    __shared__ float sbias[64];
    int tid = threadIdx.x;
    int wid = tid >> 5, lane = tid & 31;
    if (tid < 64) sbias[tid] = bias[tid];
    __syncthreads();

    int m0 = blockIdx.x * 128 + wid * 16;
    int qp = (lane & 3) * 2;
    int gi = lane >> 2;
    int r0 = m0 + gi;
    int r1 = r0 + 8;
    bool v0 = r0 < N_NODES, v1 = r1 < N_NODES;

    float acc[8][4];
    #pragma unroll
    for (int t = 0; t < 8; t++)
        #pragma unroll
        for (int i = 0; i < 4; i++) acc[t][i] = 0.f;

    #pragma unroll
    for (int kc = 0; kc < 2; kc++) {
        const __half* __restrict__ X = kc ? g_h1 : g_agg;
        const __half* __restrict__ W = &g_wT[(2 + kc) * 4096];
        #pragma unroll
        for (int ks = 0; ks < 4; ks++) {
            int kb = ks * 16;
            uint32_t a0 = 0, a1 = 0, a2 = 0, a3 = 0;
            if (v0) {
                a0 = *(const uint32_t*)&X[(size_t)r0 * 64 + kb + qp];
                a2 = *(const uint32_t*)&X[(size_t)r0 * 64 + kb + qp + 8];
            }
            if (v1) {
                a1 = *(const uint32_t*)&X[(size_t)r1 * 64 + kb + qp];
                a3 = *(const uint32_t*)&X[(size_t)r1 * 64 + kb + qp + 8];
            }
            #pragma unroll
            for (int t = 0; t < 8; t++) {
                int n = t * 8 + gi;
                uint32_t b0 = *(const uint32_t*)&W[n * 64 + kb + qp];
                uint32_t b1 = *(const uint32_t*)&W[n * 64 + kb + qp + 8];
                asm volatile(
                    "mma.sync.aligned.m16n8k16.row.col.f32.f16.f16.f32 "
                    "{%0,%1,%2,%3}, {%4,%5,%6,%7}, {%8,%9}, {%0,%1,%2,%3};"
                    : "+f"(acc[t][0]), "+f"(acc[t][1]),
                      "+f"(acc[t][2]), "+f"(acc[t][3])
                    : "r"(a0), "r"(a1), "r"(a2), "r"(a3), "r"(b0), "r"(b1));
            }
        }
    }

    int b0g = v0 ? batch[r0] : 0;
    int b1g = v1 ? batch[r1] : 0;
    #pragma unroll
    for (int t = 0; t < 8; t++) {
        int ct = t * 8 + qp;
        float bx = sbias[ct], by = sbias[ct + 1];
        float o0 = fmaxf(acc[t][0] + bx, 0.f);
        float o1 = fmaxf(acc[t][1] + by, 0.f);
        float o2 = fmaxf(acc[t][2] + bx, 0.f);
        float o3 = fmaxf(acc[t][3] + by, 0.f);
        if (v0) atomicAdd((float2*)&g_pool[b0g * 64 + ct],
                          make_float2(o0, o1));
        if (v1) atomicAdd((float2*)&g_pool[b1g * 64 + ct],
                          make_float2(o2, o3));
    }
}

// ---------------------------------------------------------------------------
__global__ void k_final(const float* __restrict__ wc,
                        const float* __restrict__ bc,
                        float* __restrict__ out) {
    int g = blockIdx.x * blockDim.x + threadIdx.x;
    if (g >= NG) return;
    float inv = 1.f / fmaxf((float)g_pcnt[g], 1.f);
    float acc[NCLS];
    #pragma unroll
    for (int c = 0; c < NCLS; c++) acc[c] = bc[c];
    for (int k = 0; k < 64; k++) {
        float p = g_pool[g * 64 + k] * inv;
        #pragma unroll
        for (int c = 0; c < NCLS; c++)
            acc[c] += p * wc[k * NCLS + c];
    }
    #pragma unroll
    for (int c = 0; c < NCLS; c++) out[g * NCLS + c] = acc[c];
}

// ---------------------------------------------------------------------------
extern "C" void kernel_launch(void* const* d_in, const int* in_sizes, int n_in,
                              void* d_out, int out_size) {
    int o = (n_in >= 14) ? 1 : 0;
    const int*   x     = (const int*)d_in[0];
    const int*   ei    = (const int*)d_in[1];
    const int*   batch = (const int*)d_in[2];
    const float* semb  = (const float*)d_in[3 + o];
    const float* cemb  = (const float*)d_in[4 + o];
    const float* w1l   = (const float*)d_in[5 + o];
    const float* w1r   = (const float*)d_in[6 + o];
    const float* b1    = (const float*)d_in[7 + o];
    const float* w2l   = (const float*)d_in[8 + o];
    const float* w2r   = (const float*)d_in[9 + o];
    const float* b2    = (const float*)d_in[10 + o];
    const float* wc    = (const float*)d_in[11 + o];
    const float* bc    = (const float*)d_in[12 + o];
    float* out = (float*)d_out;

    k_zero<<<(N_NODES + 255) / 256, 256>>>();
    k_code<<<(N_NODES + 255) / 256, 256>>>(x, batch);
    k_tab<<<(NCODE * 8 + 255) / 256, 256>>>(semb, cemb, w1l, w1r, b1);
    k_prepw<<<64, 256>>>(w1l, w1r, w2l, w2r);
    // CSR build
    k_count<<<N_EDGES / 256, 256>>>(ei);
    k_scan1<<<SCAN_NB, SCAN_BS>>>();
    k_scan2<<<1, 32>>>();
    k_scan3<<<(N_NODES + 255) / 256, 256>>>();
    k_bucket<<<N_EDGES / 256, 256>>>(ei);
    // layer 1: fully fused via code tables
    k_l1<<<(N_NODES * 32 + 255) / 256, 256>>>();
    // layer 2
    k_gather<<<(N_NODES * 32 + 255) / 256, 256>>>();
    k_upd<<<(N_NODES + 127) / 128, 256>>>(b2, batch);
    // pool -> classifier
    k_final<<<(NG + 255) / 256, 256>>>(wc, bc, out);
}

// round 11
// speedup vs baseline: 1.3649x; 1.0630x over previous
#include <cuda_runtime.h>
#include <cuda_fp16.h>
#include <cstdint>

#define N_NODES 100000
#define N_EDGES 1600000
#define HID 64
#define NG 512
#define NCLS 10
#define NCODE 1024          // 64 shapes x 16 colors
#define SCAN_BS 512
#define SCAN_NB ((N_NODES + SCAN_BS - 1) / SCAN_BS)   // 196
#define IDMASK 0xFFFFFu     // low 20 bits: node id; high bits: code

// ---------------- device scratch (no allocations allowed) -------------------
__device__ __half g_h1[N_NODES * HID];
__device__ __half g_agg[N_NODES * HID];
__device__ __half g_wT[4 * 4096];   // wT[m][n*64+k] = w[k][n], fp16 (m=2,3 used)
__device__ __align__(16) __half g_y[NCODE * HID];    // 128 KB: code -> h0@w1l (fp16)
__device__ float  g_z2[NCODE * HID];                 // 256 KB: code -> h0@w1r + b1
__device__ int   g_code[N_NODES];
__device__ int   g_cnt[N_NODES];
__device__ int   g_rowptr[N_NODES + 1];
__device__ int   g_cursor[N_NODES];
__device__ int   g_eord[N_EDGES];   // packed: src | (code<<20)
__device__ int   g_part[SCAN_NB];
__device__ float g_pool[NG * HID];
__device__ int   g_pcnt[NG];

// ---------------------------------------------------------------------------
// Zero counters/pool + per-node code + per-graph node counts (merged)
__global__ void k_init(const int* __restrict__ x,
                       const int* __restrict__ batch) {
    int i = blockIdx.x * blockDim.x + threadIdx.x;
    if (i < NG * HID) g_pool[i] = 0.f;
    if (i < NG) g_pcnt[i] = 0;
    if (i < N_NODES) {
        g_cnt[i] = 0;
        g_code[i] = x[i * 2] * 16 + x[i * 2 + 1];
    }
}
__global__ void k_pcnt(const int* __restrict__ batch) {
    int n = blockIdx.x * blockDim.x + threadIdx.x;
    if (n < N_NODES) atomicAdd(&g_pcnt[batch[n]], 1);
}

// Build code tables: y[code] = h0(code) @ w1l (fp16), z2[code] = h0@w1r + b1 (fp32)
__global__ void k_tab(const float* __restrict__ semb,
                      const float* __restrict__ cemb,
                      const float* __restrict__ w1l,
                      const float* __restrict__ w1r,
                      const float* __restrict__ b1) {
    int id = blockIdx.x * blockDim.x + threadIdx.x;
    if (id >= NCODE * 8) return;
    int code = id >> 3, jg = id & 7;
    int s = code >> 4, c = code & 15;
    float oy[8], oz[8];
    #pragma unroll
    for (int j = 0; j < 8; j++) { oy[j] = 0.f; oz[j] = 0.f; }
    for (int k = 0; k < 32; k++) {
        float a = semb[s * 32 + k];
        #pragma unroll
        for (int j = 0; j < 8; j++) {
            oy[j] += a * w1l[k * 64 + jg * 8 + j];
            oz[j] += a * w1r[k * 64 + jg * 8 + j];
        }
    }
    for (int k = 0; k < 32; k++) {
        float a = cemb[c * 32 + k];
        #pragma unroll
        for (int j = 0; j < 8; j++) {
            oy[j] += a * w1l[(32 + k) * 64 + jg * 8 + j];
            oz[j] += a * w1r[(32 + k) * 64 + jg * 8 + j];
        }
    }
    __half2 yh[4];
    #pragma unroll
    for (int q = 0; q < 4; q++)
        yh[q] = __floats2half2_rn(oy[q * 2], oy[q * 2 + 1]);
    *(uint4*)&g_y[code * 64 + jg * 8] = *(uint4*)yh;
    #pragma unroll
    for (int j = 0; j < 8; j++)
        g_z2[code * 64 + jg * 8 + j] = oz[j] + b1[jg * 8 + j];
}

// Transpose weights to k-major fp16: wT[n][k] = w[k][n].
// n innermost -> coalesced reads, scattered fp16 writes (cheap).
__global__ void k_prepw(const float* __restrict__ w0,
                        const float* __restrict__ w1,
                        const float* __restrict__ w2,
                        const float* __restrict__ w3) {
    int id = blockIdx.x * blockDim.x + threadIdx.x;   // 16384
    int m = id >> 12, r = id & 4095;
    int k = r >> 6, n = r & 63;
    const float* w = (m == 0) ? w0 : (m == 1) ? w1 : (m == 2) ? w2 : w3;
    g_wT[m * 4096 + n * 64 + k] = __float2half_rn(w[r]);
}

// In-degree histogram
__global__ void k_count(const int* __restrict__ ei) {
    int e = blockIdx.x * blockDim.x + threadIdx.x;
    atomicAdd(&g_cnt[ei[N_EDGES + e]], 1);
}

__global__ void k_scan1() {
    __shared__ int s[SCAN_BS];
    int tid = threadIdx.x;
    int i = blockIdx.x * SCAN_BS + tid;
    int v = (i < N_NODES) ? g_cnt[i] : 0;
    s[tid] = v;
    __syncthreads();
    for (int off = 1; off < SCAN_BS; off <<= 1) {
        int t = (tid >= off) ? s[tid - off] : 0;
        __syncthreads();
        s[tid] += t;
        __syncthreads();
    }
    if (i < N_NODES) g_rowptr[i] = s[tid] - v;
    if (tid == SCAN_BS - 1) g_part[blockIdx.x] = s[tid];
}

__global__ void k_scan2() {
    int lane = threadIdx.x;
    int carry = 0;
    for (int base = 0; base < SCAN_NB; base += 32) {
        int idx = base + lane;
        int orig = (idx < SCAN_NB) ? g_part[idx] : 0;
        int v = orig;
        #pragma unroll
        for (int off = 1; off < 32; off <<= 1) {
            int t = __shfl_up_sync(0xffffffffu, v, off);
            if (lane >= off) v += t;
        }
        if (idx < SCAN_NB) g_part[idx] = carry + v - orig;
        carry += __shfl_sync(0xffffffffu, v, 31);
    }
}

__global__ void k_scan3() {
    int i = blockIdx.x * blockDim.x + threadIdx.x;
    if (i < N_NODES) {
        int r = g_rowptr[i] + g_part[i / SCAN_BS];
        g_rowptr[i] = r;
        g_cursor[i] = r;
    }
    if (i == 0) g_rowptr[N_NODES] = N_EDGES;
}

// Bucket edges by target; single packed scattered store (src | code<<20)
__global__ void k_bucket(const int* __restrict__ ei) {
    int e = blockIdx.x * blockDim.x + threadIdx.x;
    int src = ei[e];
    int tgt = ei[N_EDGES + e];
    int pos = atomicAdd(&g_cursor[tgt], 1);
    g_eord[pos] = src | (g_code[src] << 20);
}

// ---------------------------------------------------------------------------
// Layer 1 (fully fused, table-based):
// h1[n] = relu( mean_{src in N(n)} y[code[src]] + z2[code[n]] )
// One warp/node, 4 edge-subgroups x 8 dim-lanes; y table is L1-resident.
__global__ void __launch_bounds__(256) k_l1(void) {
    int w = (blockIdx.x * blockDim.x + threadIdx.x) >> 5;
    int lane = threadIdx.x & 31;
    if (w >= N_NODES) return;
    int start = g_rowptr[w], end = g_rowptr[w + 1];
    int deg = end - start;
    int eg = lane >> 3;        // edge subgroup 0..3
    int dg = lane & 7;         // dim group: halves [dg*8, dg*8+8)

    float acc[8];
    #pragma unroll
    for (int i = 0; i < 8; i++) acc[i] = 0.f;

    for (int base = start; base < end; base += 32) {
        int p = base + lane;
        int ev = (p < end) ? g_eord[p] : 0;
        int m = min(32, end - base);
        int fullc = m >> 2;
        int c = 0;
        #pragma unroll 4
        for (; c < fullc; c++) {
            int code = ((unsigned)__shfl_sync(0xffffffffu, ev, c * 4 + eg)) >> 20;
            uint4 v = *(const uint4*)&g_y[code * 64 + dg * 8];
            __half2* hv = (__half2*)&v;
            #pragma unroll
            for (int q = 0; q < 4; q++) {
                float2 f = __half22float2(hv[q]);
                acc[q * 2]     += f.x;
                acc[q * 2 + 1] += f.y;
            }
        }
        if (c * 4 < m) {
            int j = c * 4 + eg;
            int code = ((unsigned)__shfl_sync(0xffffffffu, ev, j)) >> 20;
            uint4 v = *(const uint4*)&g_y[code * 64 + dg * 8];
            if (j < m) {
                __half2* hv = (__half2*)&v;
                #pragma unroll
                for (int q = 0; q < 4; q++) {
                    float2 f = __half22float2(hv[q]);
                    acc[q * 2]     += f.x;
                    acc[q * 2 + 1] += f.y;
                }
            }
        }
    }

    #pragma unroll
    for (int i = 0; i < 8; i++) {
        acc[i] += __shfl_xor_sync(0xffffffffu, acc[i], 8);
        acc[i] += __shfl_xor_sync(0xffffffffu, acc[i], 16);
    }
    if (lane < 8) {
        float inv = 1.f / (float)max(deg, 1);
        int cn = g_code[w];
        float4 z0 = *(const float4*)&g_z2[cn * 64 + dg * 8];
        float4 z1 = *(const float4*)&g_z2[cn * 64 + dg * 8 + 4];
        float o[8];
        o[0] = fmaxf(acc[0] * inv + z0.x, 0.f);
        o[1] = fmaxf(acc[1] * inv + z0.y, 0.f);
        o[2] = fmaxf(acc[2] * inv + z0.z, 0.f);
        o[3] = fmaxf(acc[3] * inv + z0.w, 0.f);
        o[4] = fmaxf(acc[4] * inv + z1.x, 0.f);
        o[5] = fmaxf(acc[5] * inv + z1.y, 0.f);
        o[6] = fmaxf(acc[6] * inv + z1.z, 0.f);
        o[7] = fmaxf(acc[7] * inv + z1.w, 0.f);
        __half2 oh[4];
        #pragma unroll
        for (int q = 0; q < 4; q++)
            oh[q] = __floats2half2_rn(o[q * 2], o[q * 2 + 1]);
        *(uint4*)&g_h1[(size_t)w * 64 + dg * 8] = *(uint4*)oh;
    }
}

// ---------------------------------------------------------------------------
// Layer-2 CSR gather (fp16): agg[n] = mean_{s in N(n)} h1[s]. One warp/node,
// 4 edge-subgroups x 8 dim-lanes, LDG.128. fp32 accum.
__global__ void __launch_bounds__(256) k_gather(void) {
    int w = (blockIdx.x * blockDim.x + threadIdx.x) >> 5;
    int lane = threadIdx.x & 31;
    if (w >= N_NODES) return;
    int start = g_rowptr[w], end = g_rowptr[w + 1];
    int deg = end - start;
    const __half* __restrict__ h = g_h1;
    int eg = lane >> 3;
    int dg = lane & 7;

    float acc[8];
    #pragma unroll
    for (int i = 0; i < 8; i++) acc[i] = 0.f;

    for (int base = start; base < end; base += 32) {
        int p = base + lane;
        int ev = (p < end) ? g_eord[p] : 0;
        int m = min(32, end - base);
        int fullc = m >> 2;
        int c = 0;
        #pragma unroll 4
        for (; c < fullc; c++) {
            int s = __shfl_sync(0xffffffffu, ev, c * 4 + eg) & IDMASK;
            uint4 v = *(const uint4*)&h[(size_t)s * 64 + dg * 8];
            __half2* hv = (__half2*)&v;
            #pragma unroll
            for (int q = 0; q < 4; q++) {
                float2 f = __half22float2(hv[q]);
                acc[q * 2]     += f.x;
                acc[q * 2 + 1] += f.y;
            }
        }
        if (c * 4 < m) {
            int j = c * 4 + eg;
            int s = __shfl_sync(0xffffffffu, ev, j) & IDMASK;
            uint4 v = *(const uint4*)&h[(size_t)s * 64 + dg * 8];
            if (j < m) {
                __half2* hv = (__half2*)&v;
                #pragma unroll
                for (int q = 0; q < 4; q++) {
                    float2 f = __half22float2(hv[q]);
                    acc[q * 2]     += f.x;
                    acc[q * 2 + 1] += f.y;
                }
            }
        }
    }

    #pragma unroll
    for (int i = 0; i < 8; i++) {
        acc[i] += __shfl_xor_sync(0xffffffffu, acc[i], 8);
        acc[i] += __shfl_xor_sync(0xffffffffu, acc[i], 16);
    }
    if (lane < 8) {
        float inv = 1.f / (float)max(deg, 1);
        __half2 o[4];
        #pragma unroll
        for (int q = 0; q < 4; q++)
            o[q] = __floats2half2_rn(acc[q * 2] * inv, acc[q * 2 + 1] * inv);
        *(uint4*)&g_agg[(size_t)w * 64 + dg * 8] = *(uint4*)o;
    }
}

// ---------------------------------------------------------------------------
// Layer-2 HMMA update + pool: pool[batch[n]] += relu(agg @ w2l + h1 @ w2r + b2)
__global__ void __launch_bounds__(256) k_upd(const float* __restrict__ bias,
                                             const int* __restrict__ batch) {
    __shared__ float sbias[64];
    int tid = threadIdx.x;
    int wid = tid >> 5, lane = tid & 31;
    if (tid < 64) sbias[tid] = bias[tid];
    __syncthreads();

    int m0 = blockIdx.x * 128 + wid * 16;
    int qp = (lane & 3) * 2;
    int gi = lane >> 2;
    int r0 = m0 + gi;
    int r1 = r0 + 8;
    bool v0 = r0 < N_NODES, v1 = r1 < N_NODES;

    float acc[8][4];
    #pragma unroll
    for (int t = 0; t < 8; t++)
        #pragma unroll
        for (int i = 0; i < 4; i++) acc[t][i] = 0.f;

    #pragma unroll
    for (int kc = 0; kc < 2; kc++) {
        const __half* __restrict__ X = kc ? g_h1 : g_agg;
        const __half* __restrict__ W = &g_wT[(2 + kc) * 4096];
        #pragma unroll
        for (int ks = 0; ks < 4; ks++) {
            int kb = ks * 16;
            uint32_t a0 = 0, a1 = 0, a2 = 0, a3 = 0;
            if (v0) {
                a0 = *(const uint32_t*)&X[(size_t)r0 * 64 + kb + qp];
                a2 = *(const uint32_t*)&X[(size_t)r0 * 64 + kb + qp + 8];
            }
            if (v1) {
                a1 = *(const uint32_t*)&X[(size_t)r1 * 64 + kb + qp];
                a3 = *(const uint32_t*)&X[(size_t)r1 * 64 + kb + qp + 8];
            }
            #pragma unroll
            for (int t = 0; t < 8; t++) {
                int n = t * 8 + gi;
                uint32_t b0 = *(const uint32_t*)&W[n * 64 + kb + qp];
                uint32_t b1 = *(const uint32_t*)&W[n * 64 + kb + qp + 8];
                asm volatile(
                    "mma.sync.aligned.m16n8k16.row.col.f32.f16.f16.f32 "
                    "{%0,%1,%2,%3}, {%4,%5,%6,%7}, {%8,%9}, {%0,%1,%2,%3};"
                    : "+f"(acc[t][0]), "+f"(acc[t][1]),
                      "+f"(acc[t][2]), "+f"(acc[t][3])
                    : "r"(a0), "r"(a1), "r"(a2), "r"(a3), "r"(b0), "r"(b1));
            }
        }
    }

    int b0g = v0 ? batch[r0] : 0;
    int b1g = v1 ? batch[r1] : 0;
    #pragma unroll
    for (int t = 0; t < 8; t++) {
        int ct = t * 8 + qp;
        float bx = sbias[ct], by = sbias[ct + 1];
        float o0 = fmaxf(acc[t][0] + bx, 0.f);
        float o1 = fmaxf(acc[t][1] + by, 0.f);
        float o2 = fmaxf(acc[t][2] + bx, 0.f);
        float o3 = fmaxf(acc[t][3] + by, 0.f);
        if (v0) atomicAdd((float2*)&g_pool[b0g * 64 + ct],
                          make_float2(o0, o1));
        if (v1) atomicAdd((float2*)&g_pool[b1g * 64 + ct],
                          make_float2(o2, o3));
    }
}

// ---------------------------------------------------------------------------
__global__ void k_final(const float* __restrict__ wc,
                        const float* __restrict__ bc,
                        float* __restrict__ out) {
    int g = blockIdx.x * blockDim.x + threadIdx.x;
    if (g >= NG) return;
    float inv = 1.f / fmaxf((float)g_pcnt[g], 1.f);
    float acc[NCLS];
    #pragma unroll
    for (int c = 0; c < NCLS; c++) acc[c] = bc[c];
    for (int k = 0; k < 64; k++) {
        float p = g_pool[g * 64 + k] * inv;
        #pragma unroll
        for (int c = 0; c < NCLS; c++)
            acc[c] += p * wc[k * NCLS + c];
    }
    #pragma unroll
    for (int c = 0; c < NCLS; c++) out[g * NCLS + c] = acc[c];
}

// ---------------------------------------------------------------------------
extern "C" void kernel_launch(void* const* d_in, const int* in_sizes, int n_in,
                              void* d_out, int out_size) {
    int o = (n_in >= 14) ? 1 : 0;
    const int*   x     = (const int*)d_in[0];
    const int*   ei    = (const int*)d_in[1];
    const int*   batch = (const int*)d_in[2];
    const float* semb  = (const float*)d_in[3 + o];
    const float* cemb  = (const float*)d_in[4 + o];
    const float* w1l   = (const float*)d_in[5 + o];
    const float* w1r   = (const float*)d_in[6 + o];
    const float* b1    = (const float*)d_in[7 + o];
    const float* w2l   = (const float*)d_in[8 + o];
    const float* w2r   = (const float*)d_in[9 + o];
    const float* b2    = (const float*)d_in[10 + o];
    const float* wc    = (const float*)d_in[11 + o];
    const float* bc    = (const float*)d_in[12 + o];
    float* out = (float*)d_out;

    k_init<<<(N_NODES + 255) / 256, 256>>>(x, batch);
    k_pcnt<<<(N_NODES + 255) / 256, 256>>>(batch);
    k_tab<<<(NCODE * 8 + 255) / 256, 256>>>(semb, cemb, w1l, w1r, b1);
    k_prepw<<<64, 256>>>(w1l, w1r, w2l, w2r);
    // CSR build
    k_count<<<N_EDGES / 256, 256>>>(ei);
    k_scan1<<<SCAN_NB, SCAN_BS>>>();
    k_scan2<<<1, 32>>>();
    k_scan3<<<(N_NODES + 255) / 256, 256>>>();
    k_bucket<<<N_EDGES / 256, 256>>>(ei);
    // layer 1: fully fused via code tables
    k_l1<<<(N_NODES * 32 + 255) / 256, 256>>>();
    // layer 2
    k_gather<<<(N_NODES * 32 + 255) / 256, 256>>>();
    k_upd<<<(N_NODES + 127) / 128, 256>>>(b2, batch);
    // pool -> classifier
    k_final<<<(NG + 255) / 256, 256>>>(wc, bc, out);
}

// round 12
// speedup vs baseline: 1.4536x; 1.0650x over previous
#include <cuda_runtime.h>
#include <cuda_fp16.h>
#include <cstdint>

#define N_NODES 100000
#define N_EDGES 1600000
#define HID 64
#define NG 512
#define NCLS 10
#define NCODE 1024          // 64 shapes x 16 colors
#define SCAN_BS 512
#define SCAN_NB ((N_NODES + SCAN_BS - 1) / SCAN_BS)   // 196
#define IDMASK 0xFFFFFu     // low 20 bits: node id; high bits: code

// ---------------- device scratch (no allocations allowed) -------------------
__device__ __half g_h1[N_NODES * HID];
__device__ __half g_agg[N_NODES * HID];
__device__ __half g_wT[4 * 4096];   // wT[m][n*64+k] = w[k][n], fp16 (m=2,3 used)
__device__ __align__(16) __half g_y[NCODE * HID];    // 128 KB: code -> h0@w1l (fp16)
__device__ float  g_z2[NCODE * HID];                 // 256 KB: code -> h0@w1r + b1
__device__ int   g_code[N_NODES];
__device__ int   g_cnt[N_NODES];
__device__ int   g_rowptr[N_NODES + 1];
__device__ int   g_cursor[N_NODES];
__device__ int   g_eord[N_EDGES];   // packed: src | (code<<20)
__device__ int   g_part[SCAN_NB];
__device__ float g_pool[NG * HID];

// ---------------------------------------------------------------------------
// Zero counters/pool + per-node code (no atomics; pcnt via binary search later)
__global__ void k_init(const int* __restrict__ x) {
    int i = blockIdx.x * blockDim.x + threadIdx.x;
    if (i < NG * HID) g_pool[i] = 0.f;
    if (i < N_NODES) {
        g_cnt[i] = 0;
        g_code[i] = x[i * 2] * 16 + x[i * 2 + 1];
    }
}

// Merged prep: threads [0, NCODE*8) build code tables (y, z2);
// threads [NCODE*8, NCODE*8+16384) transpose weights to k-major fp16.
__global__ void k_prep(const float* __restrict__ semb,
                       const float* __restrict__ cemb,
                       const float* __restrict__ w1l,
                       const float* __restrict__ w1r,
                       const float* __restrict__ b1,
                       const float* __restrict__ w2l,
                       const float* __restrict__ w2r) {
    int id = blockIdx.x * blockDim.x + threadIdx.x;
    if (id < NCODE * 8) {
        int code = id >> 3, jg = id & 7;
        int s = code >> 4, c = code & 15;
        float oy[8], oz[8];
        #pragma unroll
        for (int j = 0; j < 8; j++) { oy[j] = 0.f; oz[j] = 0.f; }
        for (int k = 0; k < 32; k++) {
            float a = semb[s * 32 + k];
            #pragma unroll
            for (int j = 0; j < 8; j++) {
                oy[j] += a * w1l[k * 64 + jg * 8 + j];
                oz[j] += a * w1r[k * 64 + jg * 8 + j];
            }
        }
        for (int k = 0; k < 32; k++) {
            float a = cemb[c * 32 + k];
            #pragma unroll
            for (int j = 0; j < 8; j++) {
                oy[j] += a * w1l[(32 + k) * 64 + jg * 8 + j];
                oz[j] += a * w1r[(32 + k) * 64 + jg * 8 + j];
            }
        }
        __half2 yh[4];
        #pragma unroll
        for (int q = 0; q < 4; q++)
            yh[q] = __floats2half2_rn(oy[q * 2], oy[q * 2 + 1]);
        *(uint4*)&g_y[code * 64 + jg * 8] = *(uint4*)yh;
        #pragma unroll
        for (int j = 0; j < 8; j++)
            g_z2[code * 64 + jg * 8 + j] = oz[j] + b1[jg * 8 + j];
    } else {
        int t = id - NCODE * 8;
        if (t < 2 * 4096) {
            int m = t >> 12, r = t & 4095;       // m: 0->w2l, 1->w2r
            int k = r >> 6, n = r & 63;
            const float* w = m ? w2r : w2l;
            g_wT[(2 + m) * 4096 + n * 64 + k] = __float2half_rn(w[r]);
        }
    }
}

// In-degree histogram
__global__ void k_count(const int* __restrict__ ei) {
    int e = blockIdx.x * blockDim.x + threadIdx.x;
    atomicAdd(&g_cnt[ei[N_EDGES + e]], 1);
}

__global__ void k_scan1() {
    __shared__ int s[SCAN_BS];
    int tid = threadIdx.x;
    int i = blockIdx.x * SCAN_BS + tid;
    int v = (i < N_NODES) ? g_cnt[i] : 0;
    s[tid] = v;
    __syncthreads();
    for (int off = 1; off < SCAN_BS; off <<= 1) {
        int t = (tid >= off) ? s[tid - off] : 0;
        __syncthreads();
        s[tid] += t;
        __syncthreads();
    }
    if (i < N_NODES) g_rowptr[i] = s[tid] - v;
    if (tid == SCAN_BS - 1) g_part[blockIdx.x] = s[tid];
}

// Merged scan2+scan3: each block redundantly scans the 196 partials in smem,
// then applies its nodes' block offsets and inits cursors.
__global__ void k_scan23() {
    __shared__ int sp[256];
    __shared__ int sx[256];
    int tid = threadIdx.x;
    int orig = (tid < SCAN_NB) ? g_part[tid] : 0;
    sp[tid] = orig;
    __syncthreads();
    for (int off = 1; off < 256; off <<= 1) {
        int t = (tid >= off) ? sp[tid - off] : 0;
        __syncthreads();
        sp[tid] += t;
        __syncthreads();
    }
    sx[tid] = sp[tid] - orig;   // exclusive prefix of partials
    __syncthreads();
    int i = blockIdx.x * blockDim.x + tid;
    if (i < N_NODES) {
        int r = g_rowptr[i] + sx[i / SCAN_BS];
        g_rowptr[i] = r;
        g_cursor[i] = r;
    }
    if (i == 0) g_rowptr[N_NODES] = N_EDGES;
}

// Bucket edges by target; single packed scattered store (src | code<<20)
__global__ void k_bucket(const int* __restrict__ ei) {
    int e = blockIdx.x * blockDim.x + threadIdx.x;
    int src = ei[e];
    int tgt = ei[N_EDGES + e];
    int pos = atomicAdd(&g_cursor[tgt], 1);
    g_eord[pos] = src | (g_code[src] << 20);
}

// ---------------------------------------------------------------------------
// Layer 1 (fully fused, table-based):
// h1[n] = relu( mean_{src in N(n)} y[code[src]] + z2[code[n]] )
// One warp/node, 4 edge-subgroups x 8 dim-lanes; y table is L1-resident.
__global__ void __launch_bounds__(256) k_l1(void) {
    int w = (blockIdx.x * blockDim.x + threadIdx.x) >> 5;
    int lane = threadIdx.x & 31;
    if (w >= N_NODES) return;
    int start = g_rowptr[w], end = g_rowptr[w + 1];
    int deg = end - start;
    int eg = lane >> 3;        // edge subgroup 0..3
    int dg = lane & 7;         // dim group: halves [dg*8, dg*8+8)

    float acc[8];
    #pragma unroll
    for (int i = 0; i < 8; i++) acc[i] = 0.f;

    for (int base = start; base < end; base += 32) {
        int p = base + lane;
        int ev = (p < end) ? g_eord[p] : 0;
        int m = min(32, end - base);
        int fullc = m >> 2;
        int c = 0;
        #pragma unroll 4
        for (; c < fullc; c++) {
            int code = ((unsigned)__shfl_sync(0xffffffffu, ev, c * 4 + eg)) >> 20;
            uint4 v = *(const uint4*)&g_y[code * 64 + dg * 8];
            __half2* hv = (__half2*)&v;
            #pragma unroll
            for (int q = 0; q < 4; q++) {
                float2 f = __half22float2(hv[q]);
                acc[q * 2]     += f.x;
                acc[q * 2 + 1] += f.y;
            }
        }
        if (c * 4 < m) {
            int j = c * 4 + eg;
            int code = ((unsigned)__shfl_sync(0xffffffffu, ev, j)) >> 20;
            uint4 v = *(const uint4*)&g_y[code * 64 + dg * 8];
            if (j < m) {
                __half2* hv = (__half2*)&v;
                #pragma unroll
                for (int q = 0; q < 4; q++) {
                    float2 f = __half22float2(hv[q]);
                    acc[q * 2]     += f.x;
                    acc[q * 2 + 1] += f.y;
                }
            }
        }
    }

    #pragma unroll
    for (int i = 0; i < 8; i++) {
        acc[i] += __shfl_xor_sync(0xffffffffu, acc[i], 8);
        acc[i] += __shfl_xor_sync(0xffffffffu, acc[i], 16);
    }
    if (lane < 8) {
        float inv = 1.f / (float)max(deg, 1);
        int cn = g_code[w];
        float4 z0 = *(const float4*)&g_z2[cn * 64 + dg * 8];
        float4 z1 = *(const float4*)&g_z2[cn * 64 + dg * 8 + 4];
        float o[8];
        o[0] = fmaxf(acc[0] * inv + z0.x, 0.f);
        o[1] = fmaxf(acc[1] * inv + z0.y, 0.f);
        o[2] = fmaxf(acc[2] * inv + z0.z, 0.f);
        o[3] = fmaxf(acc[3] * inv + z0.w, 0.f);
        o[4] = fmaxf(acc[4] * inv + z1.x, 0.f);
        o[5] = fmaxf(acc[5] * inv + z1.y, 0.f);
        o[6] = fmaxf(acc[6] * inv + z1.z, 0.f);
        o[7] = fmaxf(acc[7] * inv + z1.w, 0.f);
        __half2 oh[4];
        #pragma unroll
        for (int q = 0; q < 4; q++)
            oh[q] = __floats2half2_rn(o[q * 2], o[q * 2 + 1]);
        *(uint4*)&g_h1[(size_t)w * 64 + dg * 8] = *(uint4*)oh;
    }
}

// ---------------------------------------------------------------------------
// Layer-2 CSR gather (fp16): agg[n] = mean_{s in N(n)} h1[s]. One warp/node,
// 4 edge-subgroups x 8 dim-lanes, LDG.128. fp32 accum.
__global__ void __launch_bounds__(256) k_gather(void) {
    int w = (blockIdx.x * blockDim.x + threadIdx.x) >> 5;
    int lane = threadIdx.x & 31;
    if (w >= N_NODES) return;
    int start = g_rowptr[w], end = g_rowptr[w + 1];
    int deg = end - start;
    const __half* __restrict__ h = g_h1;
    int eg = lane >> 3;
    int dg = lane & 7;

    float acc[8];
    #pragma unroll
    for (int i = 0; i < 8; i++) acc[i] = 0.f;

    for (int base = start; base < end; base += 32) {
        int p = base + lane;
        int ev = (p < end) ? g_eord[p] : 0;
        int m = min(32, end - base);
        int fullc = m >> 2;
        int c = 0;
        #pragma unroll 4
        for (; c < fullc; c++) {
            int s = __shfl_sync(0xffffffffu, ev, c * 4 + eg) & IDMASK;
            uint4 v = *(const uint4*)&h[(size_t)s * 64 + dg * 8];
            __half2* hv = (__half2*)&v;
            #pragma unroll
            for (int q = 0; q < 4; q++) {
                float2 f = __half22float2(hv[q]);
                acc[q * 2]     += f.x;
                acc[q * 2 + 1] += f.y;
            }
        }
        if (c * 4 < m) {
            int j = c * 4 + eg;
            int s = __shfl_sync(0xffffffffu, ev, j) & IDMASK;
            uint4 v = *(const uint4*)&h[(size_t)s * 64 + dg * 8];
            if (j < m) {
                __half2* hv = (__half2*)&v;
                #pragma unroll
                for (int q = 0; q < 4; q++) {
                    float2 f = __half22float2(hv[q]);
                    acc[q * 2]     += f.x;
                    acc[q * 2 + 1] += f.y;
                }
            }
        }
    }

    #pragma unroll
    for (int i = 0; i < 8; i++) {
        acc[i] += __shfl_xor_sync(0xffffffffu, acc[i], 8);
        acc[i] += __shfl_xor_sync(0xffffffffu, acc[i], 16);
    }
    if (lane < 8) {
        float inv = 1.f / (float)max(deg, 1);
        __half2 o[4];
        #pragma unroll
        for (int q = 0; q < 4; q++)
            o[q] = __floats2half2_rn(acc[q * 2] * inv, acc[q * 2 + 1] * inv);
        *(uint4*)&g_agg[(size_t)w * 64 + dg * 8] = *(uint4*)o;
    }
}

// ---------------------------------------------------------------------------
// Layer-2 HMMA update + pool: pool[batch[n]] += relu(agg @ w2l + h1 @ w2r + b2)
__global__ void __launch_bounds__(256) k_upd(const float* __restrict__ bias,
                                             const int* __restrict__ batch) {
    __shared__ float sbias[64];
    int tid = threadIdx.x;
    int wid = tid >> 5, lane = tid & 31;
    if (tid < 64) sbias[tid] = bias[tid];
    __syncthreads();

    int m0 = blockIdx.x * 128 + wid * 16;
    int qp = (lane & 3) * 2;
    int gi = lane >> 2;
    int r0 = m0 + gi;
    int r1 = r0 + 8;
    bool v0 = r0 < N_NODES, v1 = r1 < N_NODES;

    float acc[8][4];
    #pragma unroll
    for (int t = 0; t < 8; t++)
        #pragma unroll
        for (int i = 0; i < 4; i++) acc[t][i] = 0.f;

    #pragma unroll
    for (int kc = 0; kc < 2; kc++) {
        const __half* __restrict__ X = kc ? g_h1 : g_agg;
        const __half* __restrict__ W = &g_wT[(2 + kc) * 4096];
        #pragma unroll
        for (int ks = 0; ks < 4; ks++) {
            int kb = ks * 16;
            uint32_t a0 = 0, a1 = 0, a2 = 0, a3 = 0;
            if (v0) {
                a0 = *(const uint32_t*)&X[(size_t)r0 * 64 + kb + qp];
                a2 = *(const uint32_t*)&X[(size_t)r0 * 64 + kb + qp + 8];
            }
            if (v1) {
                a1 = *(const uint32_t*)&X[(size_t)r1 * 64 + kb + qp];
                a3 = *(const uint32_t*)&X[(size_t)r1 * 64 + kb + qp + 8];
            }
            #pragma unroll
            for (int t = 0; t < 8; t++) {
                int n = t * 8 + gi;
                uint32_t b0 = *(const uint32_t*)&W[n * 64 + kb + qp];
                uint32_t b1 = *(const uint32_t*)&W[n * 64 + kb + qp + 8];
                asm volatile(
                    "mma.sync.aligned.m16n8k16.row.col.f32.f16.f16.f32 "
                    "{%0,%1,%2,%3}, {%4,%5,%6,%7}, {%8,%9}, {%0,%1,%2,%3};"
                    : "+f"(acc[t][0]), "+f"(acc[t][1]),
                      "+f"(acc[t][2]), "+f"(acc[t][3])
                    : "r"(a0), "r"(a1), "r"(a2), "r"(a3), "r"(b0), "r"(b1));
            }
        }
    }

    int b0g = v0 ? batch[r0] : 0;
    int b1g = v1 ? batch[r1] : 0;
    #pragma unroll
    for (int t = 0; t < 8; t++) {
        int ct = t * 8 + qp;
        float bx = sbias[ct], by = sbias[ct + 1];
        float o0 = fmaxf(acc[t][0] + bx, 0.f);
        float o1 = fmaxf(acc[t][1] + by, 0.f);
        float o2 = fmaxf(acc[t][2] + bx, 0.f);
        float o3 = fmaxf(acc[t][3] + by, 0.f);
        if (v0) atomicAdd((float2*)&g_pool[b0g * 64 + ct],
                          make_float2(o0, o1));
        if (v1) atomicAdd((float2*)&g_pool[b1g * 64 + ct],
                          make_float2(o2, o3));
    }
}

// ---------------------------------------------------------------------------
// Classifier; per-graph node counts via binary search over the SORTED batch.
__global__ void k_final(const int* __restrict__ batch,
                        const float* __restrict__ wc,
                        const float* __restrict__ bc,
                        float* __restrict__ out) {
    int g = blockIdx.x * blockDim.x + threadIdx.x;
    if (g >= NG) return;
    // lower_bound(g) and lower_bound(g+1)
    int lo = 0, hi = N_NODES;
    while (lo < hi) { int mid = (lo + hi) >> 1; if (batch[mid] < g) lo = mid + 1; else hi = mid; }
    int lb = lo;
    hi = N_NODES;
    while (lo < hi) { int mid = (lo + hi) >> 1; if (batch[mid] < g + 1) lo = mid + 1; else hi = mid; }
    int cnt = lo - lb;
    float inv = 1.f / fmaxf((float)cnt, 1.f);
    float acc[NCLS];
    #pragma unroll
    for (int c = 0; c < NCLS; c++) acc[c] = bc[c];
    for (int k = 0; k < 64; k++) {
        float p = g_pool[g * 64 + k] * inv;
        #pragma unroll
        for (int c = 0; c < NCLS; c++)
            acc[c] += p * wc[k * NCLS + c];
    }
    #pragma unroll
    for (int c = 0; c < NCLS; c++) out[g * NCLS + c] = acc[c];
}

// ---------------------------------------------------------------------------
extern "C" void kernel_launch(void* const* d_in, const int* in_sizes, int n_in,
                              void* d_out, int out_size) {
    int o = (n_in >= 14) ? 1 : 0;
    const int*   x     = (const int*)d_in[0];
    const int*   ei    = (const int*)d_in[1];
    const int*   batch = (const int*)d_in[2];
    const float* semb  = (const float*)d_in[3 + o];
    const float* cemb  = (const float*)d_in[4 + o];
    const float* w1l   = (const float*)d_in[5 + o];
    const float* w1r   = (const float*)d_in[6 + o];
    const float* b1    = (const float*)d_in[7 + o];
    const float* w2l   = (const float*)d_in[8 + o];
    const float* w2r   = (const float*)d_in[9 + o];
    const float* b2    = (const float*)d_in[10 + o];
    const float* wc    = (const float*)d_in[11 + o];
    const float* bc    = (const float*)d_in[12 + o];
    float* out = (float*)d_out;

    k_init<<<(N_NODES + 255) / 256, 256>>>(x);
    k_prep<<<(NCODE * 8 + 2 * 4096 + 255) / 256, 256>>>(semb, cemb, w1l, w1r,
                                                        b1, w2l, w2r);
    // CSR build
    k_count<<<N_EDGES / 256, 256>>>(ei);
    k_scan1<<<SCAN_NB, SCAN_BS>>>();
    k_scan23<<<(N_NODES + 255) / 256, 256>>>();
    k_bucket<<<N_EDGES / 256, 256>>>(ei);
    // layer 1: fully fused via code tables
    k_l1<<<(N_NODES * 32 + 255) / 256, 256>>>();
    // layer 2
    k_gather<<<(N_NODES * 32 + 255) / 256, 256>>>();
    k_upd<<<(N_NODES + 127) / 128, 256>>>(b2, batch);
    // pool -> classifier
    k_final<<<(NG + 255) / 256, 256>>>(batch, wc, bc, out);
}

// round 14
// speedup vs baseline: 1.4564x; 1.0019x over previous
#include <cuda_runtime.h>
#include <cuda_fp16.h>
#include <cstdint>

#define N_NODES 100000
#define N_EDGES 1600000
#define HID 64
#define NG 512
#define NCLS 10
#define NCODE 1024          // 64 shapes x 16 colors
#define SCAN_BS 512
#define SCAN_NB ((N_NODES + SCAN_BS - 1) / SCAN_BS)   // 196
#define IDMASK 0xFFFFFu     // low 20 bits: node id; high bits: code

#define NB_COUNT (N_EDGES / 256)                 // 6250
#define NB_CODE  ((N_NODES + 255) / 256)         // 391
#define NB_PREP  ((NCODE * 8 + 2 * 4096) / 256)  // 64

// ---------------- device scratch (no allocations allowed) -------------------
// NOTE: g_cnt and g_pool rely on zero-at-load + self-restoring kernels
// (k_scan1 zeroes g_cnt after reading; k_final zeroes g_pool after reading).
__device__ __half g_h1[N_NODES * HID];
__device__ __half g_agg[N_NODES * HID];
__device__ __half g_wT[4 * 4096];   // wT[m][n*64+k] = w[k][n], fp16 (m=2,3 used)
__device__ __align__(16) __half g_y[NCODE * HID];    // 128 KB: code -> h0@w1l (fp16)
__device__ float  g_z2[NCODE * HID];                 // 256 KB: code -> h0@w1r + b1
__device__ int   g_code[N_NODES];
__device__ int   g_cnt[N_NODES];
__device__ int   g_rowptr[N_NODES + 1];
__device__ int   g_cursor[N_NODES];
__device__ int   g_eord[N_EDGES];   // packed: src | (code<<20)
__device__ int   g_part[SCAN_NB];
__device__ float g_pool[NG * HID];

// ---------------------------------------------------------------------------
// Mega-merged prologue: [0,NB_COUNT) in-degree histogram;
// [NB_COUNT, +NB_CODE) node codes; rest: code tables + weight transpose.
// All three are data-independent; init/prep hide under count's atomics.
__global__ void k_pre(const int* __restrict__ x,
                      const int* __restrict__ ei,
                      const float* __restrict__ semb,
                      const float* __restrict__ cemb,
                      const float* __restrict__ w1l,
                      const float* __restrict__ w1r,
                      const float* __restrict__ b1,
                      const float* __restrict__ w2l,
                      const float* __restrict__ w2r) {
    int b = blockIdx.x;
    int tid = threadIdx.x;
    if (b < NB_COUNT) {
        int e = b * 256 + tid;
        atomicAdd(&g_cnt[ei[N_EDGES + e]], 1);
    } else if (b < NB_COUNT + NB_CODE) {
        int i = (b - NB_COUNT) * 256 + tid;
        if (i < N_NODES) g_code[i] = x[i * 2] * 16 + x[i * 2 + 1];
    } else {
        int id = (b - NB_COUNT - NB_CODE) * 256 + tid;
        if (id < NCODE * 8) {
            int code = id >> 3, jg = id & 7;
            int s = code >> 4, c = code & 15;
            float oy[8], oz[8];
            #pragma unroll
            for (int j = 0; j < 8; j++) { oy[j] = 0.f; oz[j] = 0.f; }
            for (int k = 0; k < 32; k++) {
                float a = semb[s * 32 + k];
                #pragma unroll
                for (int j = 0; j < 8; j++) {
                    oy[j] += a * w1l[k * 64 + jg * 8 + j];
                    oz[j] += a * w1r[k * 64 + jg * 8 + j];
                }
            }
            for (int k = 0; k < 32; k++) {
                float a = cemb[c * 32 + k];
                #pragma unroll
                for (int j = 0; j < 8; j++) {
                    oy[j] += a * w1l[(32 + k) * 64 + jg * 8 + j];
                    oz[j] += a * w1r[(32 + k) * 64 + jg * 8 + j];
                }
            }
            __half2 yh[4];
            #pragma unroll
            for (int q = 0; q < 4; q++)
                yh[q] = __floats2half2_rn(oy[q * 2], oy[q * 2 + 1]);
            *(uint4*)&g_y[code * 64 + jg * 8] = *(uint4*)yh;
            #pragma unroll
            for (int j = 0; j < 8; j++)
                g_z2[code * 64 + jg * 8 + j] = oz[j] + b1[jg * 8 + j];
        } else {
            int t = id - NCODE * 8;
            if (t < 2 * 4096) {
                int m = t >> 12, r = t & 4095;   // m: 0->w2l, 1->w2r
                int k = r >> 6, n = r & 63;
                const float* w = m ? w2r : w2l;
                g_wT[(2 + m) * 4096 + n * 64 + k] = __float2half_rn(w[r]);
            }
        }
    }
}

// Block-local exclusive scan (warp-shuffle), zeroes g_cnt after reading.
__global__ void k_scan1() {
    __shared__ int wsum[16];
    int tid = threadIdx.x, lane = tid & 31, wd = tid >> 5;
    int i = blockIdx.x * SCAN_BS + tid;
    int v = (i < N_NODES) ? g_cnt[i] : 0;
    int inc = v;
    #pragma unroll
    for (int off = 1; off < 32; off <<= 1) {
        int t = __shfl_up_sync(0xffffffffu, inc, off);
        if (lane >= off) inc += t;
    }
    if (lane == 31) wsum[wd] = inc;
    __syncthreads();
    if (wd == 0) {
        int ws = (lane < 16) ? wsum[lane] : 0;
        #pragma unroll
        for (int off = 1; off < 16; off <<= 1) {
            int t = __shfl_up_sync(0xffffffffu, ws, off);
            if (lane >= off) ws += t;
        }
        if (lane < 16) wsum[lane] = ws;   // inclusive warp totals
    }
    __syncthreads();
    int wbase = (wd == 0) ? 0 : wsum[wd - 1];
    if (i < N_NODES) {
        g_rowptr[i] = wbase + inc - v;
        g_cnt[i] = 0;                     // self-restore for next replay
    }
    if (tid == SCAN_BS - 1) g_part[blockIdx.x] = wbase + inc;
}

// Merged scan2+scan3: each block redundantly scans the 196 partials in smem,
// then applies its nodes' block offsets and inits cursors.
__global__ void k_scan23() {
    __shared__ int sp[256];
    __shared__ int sx[256];
    int tid = threadIdx.x;
    int orig = (tid < SCAN_NB) ? g_part[tid] : 0;
    sp[tid] = orig;
    __syncthreads();
    for (int off = 1; off < 256; off <<= 1) {
        int t = (tid >= off) ? sp[tid - off] : 0;
        __syncthreads();
        sp[tid] += t;
        __syncthreads();
    }
    sx[tid] = sp[tid] - orig;   // exclusive prefix of partials
    __syncthreads();
    int i = blockIdx.x * blockDim.x + tid;
    if (i < N_NODES) {
        int r = g_rowptr[i] + sx[i / SCAN_BS];
        g_rowptr[i] = r;
        g_cursor[i] = r;
    }
    if (i == 0) g_rowptr[N_NODES] = N_EDGES;
}

// Bucket edges by target; single packed scattered store (src | code<<20)
__global__ void k_bucket(const int* __restrict__ ei) {
    int e = blockIdx.x * blockDim.x + threadIdx.x;
    int src = ei[e];
    int tgt = ei[N_EDGES + e];
    int pos = atomicAdd(&g_cursor[tgt], 1);
    g_eord[pos] = src | (g_code[src] << 20);
}

// ---------------------------------------------------------------------------
// Layer 1 (fully fused, table-based):
// h1[n] = relu( mean_{src in N(n)} y[code[src]] + z2[code[n]] )
__global__ void __launch_bounds__(256) k_l1(void) {
    int w = (blockIdx.x * blockDim.x + threadIdx.x) >> 5;
    int lane = threadIdx.x & 31;
    if (w >= N_NODES) return;
    int start = g_rowptr[w], end = g_rowptr[w + 1];
    int deg = end - start;
    int eg = lane >> 3;        // edge subgroup 0..3
    int dg = lane & 7;         // dim group: halves [dg*8, dg*8+8)

    float acc[8];
    #pragma unroll
    for (int i = 0; i < 8; i++) acc[i] = 0.f;

    for (int base = start; base < end; base += 32) {
        int p = base + lane;
        int ev = (p < end) ? g_eord[p] : 0;
        int m = min(32, end - base);
        int fullc = m >> 2;
        int c = 0;
        #pragma unroll 4
        for (; c < fullc; c++) {
            int code = ((unsigned)__shfl_sync(0xffffffffu, ev, c * 4 + eg)) >> 20;
            uint4 v = *(const uint4*)&g_y[code * 64 + dg * 8];
            __half2* hv = (__half2*)&v;
            #pragma unroll
            for (int q = 0; q < 4; q++) {
                float2 f = __half22float2(hv[q]);
                acc[q * 2]     += f.x;
                acc[q * 2 + 1] += f.y;
            }
        }
        if (c * 4 < m) {
            int j = c * 4 + eg;
            int code = ((unsigned)__shfl_sync(0xffffffffu, ev, j)) >> 20;
            uint4 v = *(const uint4*)&g_y[code * 64 + dg * 8];
            if (j < m) {
                __half2* hv = (__half2*)&v;
                #pragma unroll
                for (int q = 0; q < 4; q++) {
                    float2 f = __half22float2(hv[q]);
                    acc[q * 2]     += f.x;
                    acc[q * 2 + 1] += f.y;
                }
            }
        }
    }

    #pragma unroll
    for (int i = 0; i < 8; i++) {
        acc[i] += __shfl_xor_sync(0xffffffffu, acc[i], 8);
        acc[i] += __shfl_xor_sync(0xffffffffu, acc[i], 16);
    }
    if (lane < 8) {
        float inv = 1.f / (float)max(deg, 1);
        int cn = g_code[w];
        float4 z0 = *(const float4*)&g_z2[cn * 64 + dg * 8];
        float4 z1 = *(const float4*)&g_z2[cn * 64 + dg * 8 + 4];
        float o[8];
        o[0] = fmaxf(acc[0] * inv + z0.x, 0.f);
        o[1] = fmaxf(acc[1] * inv + z0.y, 0.f);
        o[2] = fmaxf(acc[2] * inv + z0.z, 0.f);
        o[3] = fmaxf(acc[3] * inv + z0.w, 0.f);
        o[4] = fmaxf(acc[4] * inv + z1.x, 0.f);
        o[5] = fmaxf(acc[5] * inv + z1.y, 0.f);
        o[6] = fmaxf(acc[6] * inv + z1.z, 0.f);
        o[7] = fmaxf(acc[7] * inv + z1.w, 0.f);
        __half2 oh[4];
        #pragma unroll
        for (int q = 0; q < 4; q++)
            oh[q] = __floats2half2_rn(o[q * 2], o[q * 2 + 1]);
        *(uint4*)&g_h1[(size_t)w * 64 + dg * 8] = *(uint4*)oh;
    }
}

// ---------------------------------------------------------------------------
// Layer-2 CSR gather (fp16): agg[n] = mean_{s in N(n)} h1[s].
__global__ void __launch_bounds__(256) k_gather(void) {
    int w = (blockIdx.x * blockDim.x + threadIdx.x) >> 5;
    int lane = threadIdx.x & 31;
    if (w >= N_NODES) return;
    int start = g_rowptr[w], end = g_rowptr[w + 1];
    int deg = end - start;
    const __half* __restrict__ h = g_h1;
    int eg = lane >> 3;
    int dg = lane & 7;

    float acc[8];
    #pragma unroll
    for (int i = 0; i < 8; i++) acc[i] = 0.f;

    for (int base = start; base < end; base += 32) {
        int p = base + lane;
        int ev = (p < end) ? g_eord[p] : 0;
        int m = min(32, end - base);
        int fullc = m >> 2;
        int c = 0;
        #pragma unroll 4
        for (; c < fullc; c++) {
            int s = __shfl_sync(0xffffffffu, ev, c * 4 + eg) & IDMASK;
            uint4 v = *(const uint4*)&h[(size_t)s * 64 + dg * 8];
            __half2* hv = (__half2*)&v;
            #pragma unroll
            for (int q = 0; q < 4; q++) {
                float2 f = __half22float2(hv[q]);
                acc[q * 2]     += f.x;
                acc[q * 2 + 1] += f.y;
            }
        }
        if (c * 4 < m) {
            int j = c * 4 + eg;
            int s = __shfl_sync(0xffffffffu, ev, j) & IDMASK;
            uint4 v = *(const uint4*)&h[(size_t)s * 64 + dg * 8];
            if (j < m) {
                __half2* hv = (__half2*)&v;
                #pragma unroll
                for (int q = 0; q < 4; q++) {
                    float2 f = __half22float2(hv[q]);
                    acc[q * 2]     += f.x;
                    acc[q * 2 + 1] += f.y;
                }
            }
        }
    }

    #pragma unroll
    for (int i = 0; i < 8; i++) {
        acc[i] += __shfl_xor_sync(0xffffffffu, acc[i], 8);
        acc[i] += __shfl_xor_sync(0xffffffffu, acc[i], 16);
    }
    if (lane < 8) {
        float inv = 1.f / (float)max(deg, 1);
        __half2 o[4];
        #pragma unroll
        for (int q = 0; q < 4; q++)
            o[q] = __floats2half2_rn(acc[q * 2] * inv, acc[q * 2 + 1] * inv);
        *(uint4*)&g_agg[(size_t)w * 64 + dg * 8] = *(uint4*)o;
    }
}

// ---------------------------------------------------------------------------
// Layer-2 HMMA update + pool. Warp-uniform pooling: when a warp's 16 rows
// belong to one graph (batch is sorted), reduce in-warp (3 shfl-xor rounds)
// and issue 8 float2 atomics from lanes 0-3 instead of 512.
__global__ void __launch_bounds__(256) k_upd(const float* __restrict__ bias,
                                             const int* __restrict__ batch) {
    __shared__ float sbias[64];
    int tid = threadIdx.x;
    int wid = tid >> 5, lane = tid & 31;
    if (tid < 64) sbias[tid] = bias[tid];
    __syncthreads();

    int m0 = blockIdx.x * 128 + wid * 16;
    int qp = (lane & 3) * 2;
    int gi = lane >> 2;
    int r0 = m0 + gi;
    int r1 = r0 + 8;
    bool v0 = r0 < N_NODES, v1 = r1 < N_NODES;

    float acc[8][4];
    #pragma unroll
    for (int t = 0; t < 8; t++)
        #pragma unroll
        for (int i = 0; i < 4; i++) acc[t][i] = 0.f;

    #pragma unroll
    for (int kc = 0; kc < 2; kc++) {
        const __half* __restrict__ X = kc ? g_h1 : g_agg;
        const __half* __restrict__ W = &g_wT[(2 + kc) * 4096];
        #pragma unroll
        for (int ks = 0; ks < 4; ks++) {
            int kb = ks * 16;
            uint32_t a0 = 0, a1 = 0, a2 = 0, a3 = 0;
            if (v0) {
                a0 = *(const uint32_t*)&X[(size_t)r0 * 64 + kb + qp];
                a2 = *(const uint32_t*)&X[(size_t)r0 * 64 + kb + qp + 8];
            }
            if (v1) {
                a1 = *(const uint32_t*)&X[(size_t)r1 * 64 + kb + qp];
                a3 = *(const uint32_t*)&X[(size_t)r1 * 64 + kb + qp + 8];
            }
            #pragma unroll
            for (int t = 0; t < 8; t++) {
                int n = t * 8 + gi;
                uint32_t b0 = *(const uint32_t*)&W[n * 64 + kb + qp];
                uint32_t b1 = *(const uint32_t*)&W[n * 64 + kb + qp + 8];
                asm volatile(
                    "mma.sync.aligned.m16n8k16.row.col.f32.f16.f16.f32 "
                    "{%0,%1,%2,%3}, {%4,%5,%6,%7}, {%8,%9}, {%0,%1,%2,%3};"
                    : "+f"(acc[t][0]), "+f"(acc[t][1]),
                      "+f"(acc[t][2]), "+f"(acc[t][3])
                    : "r"(a0), "r"(a1), "r"(a2), "r"(a3), "r"(b0), "r"(b1));
            }
        }
    }

    // bias + relu
    #pragma unroll
    for (int t = 0; t < 8; t++) {
        int ct = t * 8 + qp;
        float bx = sbias[ct], by = sbias[ct + 1];
        acc[t][0] = fmaxf(acc[t][0] + bx, 0.f);
        acc[t][1] = fmaxf(acc[t][1] + by, 0.f);
        acc[t][2] = fmaxf(acc[t][2] + bx, 0.f);
        acc[t][3] = fmaxf(acc[t][3] + by, 0.f);
    }

    bool uni = (m0 + 15 < N_NODES) && (batch[m0] == batch[m0 + 15]);
    if (uni) {
        int bg = batch[m0];
        #pragma unroll
        for (int t = 0; t < 8; t++) {
            float s0 = acc[t][0] + acc[t][2];
            float s1 = acc[t][1] + acc[t][3];
            s0 += __shfl_xor_sync(0xffffffffu, s0, 4);
            s1 += __shfl_xor_sync(0xffffffffu, s1, 4);
            s0 += __shfl_xor_sync(0xffffffffu, s0, 8);
            s1 += __shfl_xor_sync(0xffffffffu, s1, 8);
            s0 += __shfl_xor_sync(0xffffffffu, s0, 16);
            s1 += __shfl_xor_sync(0xffffffffu, s1, 16);
            if (lane < 4)
                atomicAdd((float2*)&g_pool[bg * 64 + t * 8 + qp],
                          make_float2(s0, s1));
        }
    } else {
        int b0g = v0 ? batch[r0] : 0;
        int b1g = v1 ? batch[r1] : 0;
        #pragma unroll
        for (int t = 0; t < 8; t++) {
            int ct = t * 8 + qp;
            if (v0) atomicAdd((float2*)&g_pool[b0g * 64 + ct],
                              make_float2(acc[t][0], acc[t][1]));
            if (v1) atomicAdd((float2*)&g_pool[b1g * 64 + ct],
                              make_float2(acc[t][2], acc[t][3]));
        }
    }
}

// ---------------------------------------------------------------------------
// Classifier; per-graph counts via binary search (batch sorted).
// Zeroes g_pool after reading (self-restore for next replay).
__global__ void k_final(const int* __restrict__ batch,
                        const float* __restrict__ wc,
                        const float* __restrict__ bc,
                        float* __restrict__ out) {
    int g = blockIdx.x * blockDim.x + threadIdx.x;
    if (g >= NG) return;
    int lo = 0, hi = N_NODES;
    while (lo < hi) { int mid = (lo + hi) >> 1; if (batch[mid] < g) lo = mid + 1; else hi = mid; }
    int lb = lo;
    hi = N_NODES;
    while (lo < hi) { int mid = (lo + hi) >> 1; if (batch[mid] < g + 1) lo = mid + 1; else hi = mid; }
    int cnt = lo - lb;
    float inv = 1.f / fmaxf((float)cnt, 1.f);
    float acc[NCLS];
    #pragma unroll
    for (int c = 0; c < NCLS; c++) acc[c] = bc[c];
    for (int k = 0; k < 64; k++) {
        float p = g_pool[g * 64 + k] * inv;
        g_pool[g * 64 + k] = 0.f;          // self-restore
        #pragma unroll
        for (int c = 0; c < NCLS; c++)
            acc[c] += p * wc[k * NCLS + c];
    }
    #pragma unroll
    for (int c = 0; c < NCLS; c++) out[g * NCLS + c] = acc[c];
}

// ---------------------------------------------------------------------------
extern "C" void kernel_launch(void* const* d_in, const int* in_sizes, int n_in,
                              void* d_out, int out_size) {
    int o = (n_in >= 14) ? 1 : 0;
    const int*   x     = (const int*)d_in[0];
    const int*   ei    = (const int*)d_in[1];
    const int*   batch = (const int*)d_in[2];
    const float* semb  = (const float*)d_in[3 + o];
    const float* cemb  = (const float*)d_in[4 + o];
    const float* w1l   = (const float*)d_in[5 + o];
    const float* w1r   = (const float*)d_in[6 + o];
    const float* b1    = (const float*)d_in[7 + o];
    const float* w2l   = (const float*)d_in[8 + o];
    const float* w2r   = (const float*)d_in[9 + o];
    const float* b2    = (const float*)d_in[10 + o];
    const float* wc    = (const float*)d_in[11 + o];
    const float* bc    = (const float*)d_in[12 + o];
    float* out = (float*)d_out;

    k_pre<<<NB_COUNT + NB_CODE + NB_PREP, 256>>>(x, ei, semb, cemb,
                                                 w1l, w1r, b1, w2l, w2r);
    k_scan1<<<SCAN_NB, SCAN_BS>>>();
    k_scan23<<<(N_NODES + 255) / 256, 256>>>();
    k_bucket<<<N_EDGES / 256, 256>>>(ei);
    // layer 1: fully fused via code tables
    k_l1<<<(N_NODES * 32 + 255) / 256, 256>>>();
    // layer 2
    k_gather<<<(N_NODES * 32 + 255) / 256, 256>>>();
    k_upd<<<(N_NODES + 127) / 128, 256>>>(b2, batch);
    // pool -> classifier
    k_final<<<(NG + 255) / 256, 256>>>(batch, wc, bc, out);
}